// round 12
// baseline (speedup 1.0000x reference)
#include <cuda_runtime.h>
#include <cuda_bf16.h>
#include <mma.h>
#include <math.h>

using namespace nvcuda;

// ---------------------------------------------------------------------------
// HeteroGAT encoder.
//   - 6 GEMMs via bf16 split-3 WMMA, W resident in smem; 512 threads/CTA
//     (16 warps, 32x32 warp tiles) to cover HMMA+LDSM latency
//   - CSR-by-dst; fused aggregate + softmax + LN + relu + residual
//   - multi-stream graph parallelism (A-pipe / B-pipe / CSR+wp)
//   - tcgen05 is NOT available (harness emits compute_103 PTX, no 'a' features)
// ---------------------------------------------------------------------------

#define NMAX 50176
#define EMAX 500000

__device__ float g_hA[NMAX * 128];
__device__ float g_hB[NMAX * 128];
__device__ float g_t1[NMAX * 128];
__device__ float g_t2[NMAX * 128];
__device__ float g_t3[NMAX * 128];
__device__ float g_t4[NMAX * 128];
__device__ float g_as1_0[NMAX * 4], g_ad1_0[NMAX * 4];
__device__ float g_as2_0[NMAX * 4], g_ad2_0[NMAX * 4];
__device__ float g_as1_1[NMAX], g_ad1_1[NMAX];
__device__ float g_as2_1[NMAX], g_ad2_1[NMAX];
__device__ float g_wp[8][128 * 4];
__device__ int g_rpAB[NMAX + 1], g_rpBA[NMAX + 1];
__device__ int g_cur[NMAX], g_deg[NMAX];
__device__ int g_srcAB[EMAX], g_srcBA[EMAX];

__device__ __forceinline__ float warpSum(float v) {
#pragma unroll
    for (int o = 16; o > 0; o >>= 1) v += __shfl_xor_sync(0xffffffffu, v, o);
    return v;
}
__device__ __forceinline__ float warpMax(float v) {
#pragma unroll
    for (int o = 16; o > 0; o >>= 1) v = fmaxf(v, __shfl_xor_sync(0xffffffffu, v, o));
    return v;
}

// ---------------------------------------------------------------------------
// bf16 split-3 WMMA GEMM, persistent CTAs, W resident in smem, 512 threads.
// out[M,128] = X[M,K] @ W[K,128] (+ bias). K in {64,128}. out NMAX-padded.
// ---------------------------------------------------------------------------
template <int K>
__global__ __launch_bounds__(512) void gemm_wres(
    const float* __restrict__ X, const float* __restrict__ W,
    const float* __restrict__ bias, float* __restrict__ out, int M) {
    constexpr int WLD = 136;
    constexpr int XLD = K + 8;
    constexpr int SPR = K / 4;

    extern __shared__ __nv_bfloat16 smx[];
    __nv_bfloat16* Whi = smx;
    __nv_bfloat16* Wlo = Whi + K * WLD;
    __nv_bfloat16* Xhi = Wlo + K * WLD;
    __nv_bfloat16* Xlo = Xhi + 128 * XLD;
    __shared__ float Bs[16][WLD];

    const int tid = threadIdx.x;
    const int wid = tid >> 5;                 // 0..15
    const int warp_row = (wid >> 2) * 32;     // 0,32,64,96
    const int warp_col = (wid & 3) * 32;      // 0,32,64,96

    if (bias) {
        for (int i = tid; i < 16 * 128; i += 512) Bs[i >> 7][i & 127] = bias[i & 127];
    }
    for (int idx = tid; idx < K * 32; idx += 512) {
        int r = idx >> 5;
        int c4 = (idx & 31) * 4;
        float4 v = *(const float4*)&W[(size_t)r * 128 + c4];
        float vv[4] = {v.x, v.y, v.z, v.w};
        __nv_bfloat16 h[4], l[4];
#pragma unroll
        for (int q = 0; q < 4; q++) {
            h[q] = __float2bfloat16(vv[q]);
            l[q] = __float2bfloat16(vv[q] - __bfloat162float(h[q]));
        }
        *(__nv_bfloat162*)&Whi[r * WLD + c4] = __nv_bfloat162{h[0], h[1]};
        *(__nv_bfloat162*)&Whi[r * WLD + c4 + 2] = __nv_bfloat162{h[2], h[3]};
        *(__nv_bfloat162*)&Wlo[r * WLD + c4] = __nv_bfloat162{l[0], l[1]};
        *(__nv_bfloat162*)&Wlo[r * WLD + c4 + 2] = __nv_bfloat162{l[2], l[3]};
    }
    __syncthreads();

    const int nTiles = (M + 127) >> 7;
    for (int t = blockIdx.x; t < nTiles; t += gridDim.x) {
        const int block_row = t * 128;
#pragma unroll
        for (int p = 0; p < 128 * SPR / 512; p++) {
            int idx = tid + p * 512;
            int r = idx / SPR;
            int c4 = (idx % SPR) * 4;
            int gr = block_row + r;
            float4 v = make_float4(0.f, 0.f, 0.f, 0.f);
            if (gr < M) v = *(const float4*)&X[(size_t)gr * K + c4];
            float vv[4] = {v.x, v.y, v.z, v.w};
            __nv_bfloat16 h[4], l[4];
#pragma unroll
            for (int q = 0; q < 4; q++) {
                h[q] = __float2bfloat16(vv[q]);
                l[q] = __float2bfloat16(vv[q] - __bfloat162float(h[q]));
            }
            *(__nv_bfloat162*)&Xhi[r * XLD + c4] = __nv_bfloat162{h[0], h[1]};
            *(__nv_bfloat162*)&Xhi[r * XLD + c4 + 2] = __nv_bfloat162{h[2], h[3]};
            *(__nv_bfloat162*)&Xlo[r * XLD + c4] = __nv_bfloat162{l[0], l[1]};
            *(__nv_bfloat162*)&Xlo[r * XLD + c4 + 2] = __nv_bfloat162{l[2], l[3]};
        }
        __syncthreads();

        wmma::fragment<wmma::accumulator, 16, 16, 16, float> acc[2][2];
#pragma unroll
        for (int i = 0; i < 2; i++)
#pragma unroll
            for (int j = 0; j < 2; j++) {
                if (bias)
                    wmma::load_matrix_sync(acc[i][j], &Bs[0][warp_col + j * 16], WLD,
                                           wmma::mem_row_major);
                else
                    wmma::fill_fragment(acc[i][j], 0.f);
            }

#pragma unroll 2
        for (int ks = 0; ks < K; ks += 16) {
            wmma::fragment<wmma::matrix_a, 16, 16, 16, __nv_bfloat16, wmma::row_major> ahi[2], alo[2];
            wmma::fragment<wmma::matrix_b, 16, 16, 16, __nv_bfloat16, wmma::row_major> bhi[2], blo[2];
#pragma unroll
            for (int i = 0; i < 2; i++) {
                wmma::load_matrix_sync(ahi[i], &Xhi[(warp_row + i * 16) * XLD + ks], XLD);
                wmma::load_matrix_sync(alo[i], &Xlo[(warp_row + i * 16) * XLD + ks], XLD);
            }
#pragma unroll
            for (int j = 0; j < 2; j++) {
                wmma::load_matrix_sync(bhi[j], &Whi[ks * WLD + warp_col + j * 16], WLD);
                wmma::load_matrix_sync(blo[j], &Wlo[ks * WLD + warp_col + j * 16], WLD);
            }
#pragma unroll
            for (int i = 0; i < 2; i++)
#pragma unroll
                for (int j = 0; j < 2; j++) {
                    wmma::mma_sync(acc[i][j], ahi[i], blo[j], acc[i][j]);
                    wmma::mma_sync(acc[i][j], alo[i], bhi[j], acc[i][j]);
                    wmma::mma_sync(acc[i][j], ahi[i], bhi[j], acc[i][j]);
                }
        }

#pragma unroll
        for (int i = 0; i < 2; i++)
#pragma unroll
            for (int j = 0; j < 2; j++) {
                size_t off = (size_t)(block_row + warp_row + i * 16) * 128 + warp_col + j * 16;
                wmma::store_matrix_sync(&out[off], acc[i][j], 128, wmma::mem_row_major);
            }
        __syncthreads();
    }
}

template <int K>
constexpr int gemm_smem_bytes() {
    return (2 * K * 136 + 2 * 128 * (K + 8)) * (int)sizeof(__nv_bfloat16);
}

// ---------------------------------------------------------------------------
__global__ void make_wp_all(
    const float* __restrict__ w0ab, const float* __restrict__ as0ab, const float* __restrict__ ad0ab,
    const float* __restrict__ w0ba, const float* __restrict__ as0ba, const float* __restrict__ ad0ba,
    const float* __restrict__ w1ab, const float* __restrict__ as1ab, const float* __restrict__ ad1ab,
    const float* __restrict__ w1ba, const float* __restrict__ as1ba, const float* __restrict__ ad1ba) {
    __shared__ float Ws[64][129];
    int cfg = blockIdx.x;
    const float* W = cfg == 0 ? w0ab : cfg == 1 ? w0ba : cfg == 2 ? w1ab : w1ba;
    const float* avs = cfg == 0 ? as0ab : cfg == 1 ? as0ba : cfg == 2 ? as1ab : as1ba;
    const float* avd = cfg == 0 ? ad0ab : cfg == 1 ? ad0ba : cfg == 2 ? ad1ab : ad1ba;
    const int H = (cfg < 2) ? 4 : 1;
    const int D = 128 / H;
    float* wpS = g_wp[cfg * 2];
    float* wpD = g_wp[cfg * 2 + 1];

    int tid = threadIdx.x;
    float ss[4] = {0.f, 0.f, 0.f, 0.f}, sd[4] = {0.f, 0.f, 0.f, 0.f};
    for (int chunk = 0; chunk < 2; chunk++) {
        int r0 = chunk * 64;
        for (int i = tid; i < 64 * 128; i += 256)
            Ws[i >> 7][i & 127] = W[(size_t)(r0 + (i >> 7)) * 128 + (i & 127)];
        __syncthreads();
        int k = tid;
        if (k < 128 && k >= r0 && k < r0 + 64) {
            for (int h = 0; h < H; h++) {
                float a = 0.f, b = 0.f;
                for (int d = 0; d < D; d++) {
                    float w = Ws[k - r0][h * D + d];
                    a += w * avs[h * D + d];
                    b += w * avd[h * D + d];
                }
                ss[h] = a; sd[h] = b;
            }
        }
        __syncthreads();
    }
    if (tid < 128)
        for (int h = 0; h < H; h++) { wpS[tid * H + h] = ss[h]; wpD[tid * H + h] = sd[h]; }
}

// ---------------------------------------------------------------------------
template <int H>
__global__ void node_scores2(const float* __restrict__ X, const float* __restrict__ wpS,
                             const float* __restrict__ wpD, float* __restrict__ outS,
                             float* __restrict__ outD, int N) {
    int w = (blockIdx.x * blockDim.x + threadIdx.x) >> 5;
    int lane = threadIdx.x & 31;
    if (w >= N) return;
    const float* xr = X + (size_t)w * 128;
    float accS[H], accD[H];
#pragma unroll
    for (int h = 0; h < H; h++) { accS[h] = 0.f; accD[h] = 0.f; }
#pragma unroll
    for (int kk = 0; kk < 4; kk++) {
        int k = lane + kk * 32;
        float x = xr[k];
#pragma unroll
        for (int h = 0; h < H; h++) {
            accS[h] += x * wpS[k * H + h];
            accD[h] += x * wpD[k * H + h];
        }
    }
#pragma unroll
    for (int h = 0; h < H; h++) { accS[h] = warpSum(accS[h]); accD[h] = warpSum(accD[h]); }
    if (lane == 0) {
#pragma unroll
        for (int h = 0; h < H; h++) { outS[w * H + h] = accS[h]; outD[w * H + h] = accD[h]; }
    }
}

// ---------------------------------------------------------------------------
__global__ void edge_hist(const int* __restrict__ dst, int* __restrict__ deg, int E) {
    int e = blockIdx.x * blockDim.x + threadIdx.x;
    if (e < E) atomicAdd(&deg[dst[e]], 1);
}
__global__ void edge_fill(const int* __restrict__ src, const int* __restrict__ dst,
                          int* __restrict__ cursor, int* __restrict__ col, int E) {
    int e = blockIdx.x * blockDim.x + threadIdx.x;
    if (e < E) {
        int p = atomicAdd(&cursor[dst[e]], 1);
        col[p] = src[e];
    }
}
__global__ __launch_bounds__(1024) void exscan_block(
    const int* __restrict__ deg, int* __restrict__ rowptr, int* __restrict__ cursor, int N) {
    __shared__ int sums[1024];
    int t = threadIdx.x;
    int chunk = (N + 1023) / 1024;
    int b0 = t * chunk;
    int b1 = min(b0 + chunk, N);
    int s = 0;
    for (int i = b0; i < b1; i++) s += deg[i];
    sums[t] = s;
    __syncthreads();
    for (int off = 1; off < 1024; off <<= 1) {
        int v = (t >= off) ? sums[t - off] : 0;
        __syncthreads();
        sums[t] += v;
        __syncthreads();
    }
    int run = (t == 0) ? 0 : sums[t - 1];
    for (int i = b0; i < b1; i++) {
        rowptr[i] = run;
        cursor[i] = run;
        run += deg[i];
    }
    if (t == 1023) rowptr[N] = run;
}
__global__ void zero_int(int* __restrict__ p, int n) {
    int i = blockIdx.x * blockDim.x + threadIdx.x;
    if (i < n) p[i] = 0;
}

// ---------------------------------------------------------------------------
// fused GAT aggregate + softmax + bias + LN + relu + residual (+ next scores)
// ---------------------------------------------------------------------------
template <int H, bool SC>
__global__ __launch_bounds__(256) void gat_fused(
    const int* __restrict__ rowptr, const int* __restrict__ srcs,
    const float* __restrict__ a_s, const float* __restrict__ a_d,
    const float* __restrict__ tS, const float* __restrict__ gbias,
    const float* __restrict__ gamma, const float* __restrict__ beta,
    const float* __restrict__ hprev, float* __restrict__ hout,
    const float* __restrict__ wpSn, const float* __restrict__ wpDn,
    float* __restrict__ outSn, float* __restrict__ outDn, int Ndst) {
    const int D = 128 / H;
    const int CAP = 64;
    __shared__ float s_ex[8][CAP * H];
    __shared__ int s_src[8][CAP];

    int wid = (blockIdx.x * blockDim.x + threadIdx.x) >> 5;
    int w = threadIdx.x >> 5;
    int lane = threadIdx.x & 31;
    if (wid >= Ndst) return;
    int start = rowptr[wid];
    int end = rowptr[wid + 1];
    int deg = end - start;

    float adh[H];
#pragma unroll
    for (int h = 0; h < H; h++) adh[h] = a_d[wid * H + h];

    const int hh = (lane * 4) / D;
    float4 acc = make_float4(0.f, 0.f, 0.f, 0.f);

    if (deg <= CAP) {
        float sc[2][H];
        int nIt = (deg + 31) >> 5;
        float mx[H];
#pragma unroll
        for (int h = 0; h < H; h++) mx[h] = -3.0e38f;
#pragma unroll
        for (int i = 0; i < 2; i++) {
            int j = lane + i * 32;
            if (i < nIt && j < deg) {
                int s = srcs[start + j];
                s_src[w][j] = s;
#pragma unroll
                for (int h = 0; h < H; h++) {
                    float v = a_s[s * H + h] + adh[h];
                    v = v > 0.f ? v : 0.2f * v;
                    sc[i][h] = v;
                    mx[h] = fmaxf(mx[h], v);
                }
            }
        }
#pragma unroll
        for (int h = 0; h < H; h++) mx[h] = warpMax(mx[h]);

        float sm[H];
#pragma unroll
        for (int h = 0; h < H; h++) sm[h] = 0.f;
#pragma unroll
        for (int i = 0; i < 2; i++) {
            int j = lane + i * 32;
            if (i < nIt && j < deg) {
#pragma unroll
                for (int h = 0; h < H; h++) {
                    float ex = __expf(sc[i][h] - mx[h]);
                    sm[h] += ex;
                    s_ex[w][j * H + h] = ex;
                }
            }
        }
#pragma unroll
        for (int h = 0; h < H; h++) sm[h] = warpSum(sm[h]);
        float invh;
        if (H == 1) invh = 1.f / (sm[0] + 1e-16f);
        else invh = 1.f / ((hh == 0 ? sm[0] : hh == 1 ? sm[1] : hh == 2 ? sm[2] : sm[3]) + 1e-16f);

        __syncwarp();
        int e = 0;
        for (; e + 4 <= deg; e += 4) {
            float ex0 = s_ex[w][(e + 0) * H + hh];
            float ex1 = s_ex[w][(e + 1) * H + hh];
            float ex2 = s_ex[w][(e + 2) * H + hh];
            float ex3 = s_ex[w][(e + 3) * H + hh];
            int s0 = s_src[w][e + 0], s1 = s_src[w][e + 1];
            int s2 = s_src[w][e + 2], s3 = s_src[w][e + 3];
            float4 v0 = *(const float4*)(tS + (size_t)s0 * 128 + lane * 4);
            float4 v1 = *(const float4*)(tS + (size_t)s1 * 128 + lane * 4);
            float4 v2 = *(const float4*)(tS + (size_t)s2 * 128 + lane * 4);
            float4 v3 = *(const float4*)(tS + (size_t)s3 * 128 + lane * 4);
            acc.x += v0.x * ex0 + v1.x * ex1 + v2.x * ex2 + v3.x * ex3;
            acc.y += v0.y * ex0 + v1.y * ex1 + v2.y * ex2 + v3.y * ex3;
            acc.z += v0.z * ex0 + v1.z * ex1 + v2.z * ex2 + v3.z * ex3;
            acc.w += v0.w * ex0 + v1.w * ex1 + v2.w * ex2 + v3.w * ex3;
        }
        for (; e < deg; e++) {
            float ex = s_ex[w][e * H + hh];
            int s = s_src[w][e];
            float4 v = *(const float4*)(tS + (size_t)s * 128 + lane * 4);
            acc.x += v.x * ex; acc.y += v.y * ex; acc.z += v.z * ex; acc.w += v.w * ex;
        }
        acc.x *= invh; acc.y *= invh; acc.z *= invh; acc.w *= invh;
    } else {
        float mx[H];
#pragma unroll
        for (int h = 0; h < H; h++) mx[h] = -3.0e38f;
        for (int e = start + lane; e < end; e += 32) {
            int s = srcs[e];
#pragma unroll
            for (int h = 0; h < H; h++) {
                float v = a_s[s * H + h] + adh[h];
                v = v > 0.f ? v : 0.2f * v;
                mx[h] = fmaxf(mx[h], v);
            }
        }
#pragma unroll
        for (int h = 0; h < H; h++) mx[h] = warpMax(mx[h]);
        float sm[H];
#pragma unroll
        for (int h = 0; h < H; h++) sm[h] = 0.f;
        for (int e = start + lane; e < end; e += 32) {
            int s = srcs[e];
#pragma unroll
            for (int h = 0; h < H; h++) {
                float v = a_s[s * H + h] + adh[h];
                v = v > 0.f ? v : 0.2f * v;
                sm[h] += __expf(v - mx[h]);
            }
        }
#pragma unroll
        for (int h = 0; h < H; h++) sm[h] = warpSum(sm[h]);
        float invh;
        if (H == 1) invh = 1.f / (sm[0] + 1e-16f);
        else invh = 1.f / ((hh == 0 ? sm[0] : hh == 1 ? sm[1] : hh == 2 ? sm[2] : sm[3]) + 1e-16f);
        float mxh = (H == 1) ? mx[0] : (hh == 0 ? mx[0] : hh == 1 ? mx[1] : hh == 2 ? mx[2] : mx[3]);
        float adhh = (H == 1) ? adh[0] : (hh == 0 ? adh[0] : hh == 1 ? adh[1] : hh == 2 ? adh[2] : adh[3]);
        for (int e = start; e < end; e++) {
            int s = srcs[e];
            float v = a_s[s * H + hh] + adhh;
            v = v > 0.f ? v : 0.2f * v;
            float ex = __expf(v - mxh);
            float4 t = *(const float4*)(tS + (size_t)s * 128 + lane * 4);
            acc.x += t.x * ex; acc.y += t.y * ex; acc.z += t.z * ex; acc.w += t.w * ex;
        }
        acc.x *= invh; acc.y *= invh; acc.z *= invh; acc.w *= invh;
    }

    size_t rbase = (size_t)wid * 128 + lane * 4;
    float4 bb = *(const float4*)(gbias + lane * 4);
    acc.x += bb.x; acc.y += bb.y; acc.z += bb.z; acc.w += bb.w;
    float mu = warpSum(acc.x + acc.y + acc.z + acc.w) * (1.f / 128.f);
    float dx = acc.x - mu, dy = acc.y - mu, dz = acc.z - mu, dw = acc.w - mu;
    float var = warpSum(dx * dx + dy * dy + dz * dz + dw * dw) * (1.f / 128.f);
    float r = rsqrtf(var + 1e-5f);
    float4 gg = *(const float4*)(gamma + lane * 4);
    float4 be = *(const float4*)(beta + lane * 4);
    float4 hp = *(const float4*)(hprev + rbase);
    float4 o;
    o.x = fmaxf(0.f, dx * r * gg.x + be.x) + hp.x;
    o.y = fmaxf(0.f, dy * r * gg.y + be.y) + hp.y;
    o.z = fmaxf(0.f, dz * r * gg.z + be.z) + hp.z;
    o.w = fmaxf(0.f, dw * r * gg.w + be.w) + hp.w;
    *(float4*)(hout + rbase) = o;

    if (SC) {
        float4 ws = *(const float4*)(wpSn + lane * 4);
        float4 wd = *(const float4*)(wpDn + lane * 4);
        float sS = o.x * ws.x + o.y * ws.y + o.z * ws.z + o.w * ws.w;
        float sD = o.x * wd.x + o.y * wd.y + o.z * wd.z + o.w * wd.w;
        sS = warpSum(sS);
        sD = warpSum(sD);
        if (lane == 0) { outSn[wid] = sS; outDn[wid] = sD; }
    }
}

// ---------------------------------------------------------------------------
static inline void* sym(const void* s) {
    void* p = nullptr;
    cudaGetSymbolAddress(&p, s);
    return p;
}

extern "C" void kernel_launch(void* const* d_in, const int* in_sizes, int n_in,
                              void* d_out, int out_size) {
    const float* x_A = (const float*)d_in[0];
    const float* x_B = (const float*)d_in[1];
    const float* pWA = (const float*)d_in[2];
    const float* pbA = (const float*)d_in[3];
    const float* pWB = (const float*)d_in[4];
    const float* pbB = (const float*)d_in[5];
    const float* w0ab = (const float*)d_in[6];
    const float* as0ab = (const float*)d_in[7];
    const float* ad0ab = (const float*)d_in[8];
    const float* b0ab = (const float*)d_in[9];
    const float* w0ba = (const float*)d_in[10];
    const float* as0ba = (const float*)d_in[11];
    const float* ad0ba = (const float*)d_in[12];
    const float* b0ba = (const float*)d_in[13];
    const float* w1ab = (const float*)d_in[14];
    const float* as1ab = (const float*)d_in[15];
    const float* ad1ab = (const float*)d_in[16];
    const float* b1ab = (const float*)d_in[17];
    const float* w1ba = (const float*)d_in[18];
    const float* as1ba = (const float*)d_in[19];
    const float* ad1ba = (const float*)d_in[20];
    const float* b1ba = (const float*)d_in[21];
    const float* g0A = (const float*)d_in[22];
    const float* bn0A = (const float*)d_in[23];
    const float* g0B = (const float*)d_in[24];
    const float* bn0B = (const float*)d_in[25];
    const float* g1A = (const float*)d_in[26];
    const float* bn1A = (const float*)d_in[27];
    const float* g1B = (const float*)d_in[28];
    const float* bn1B = (const float*)d_in[29];
    const int* ei_AB = (const int*)d_in[30];
    const int* ei_BA = (const int*)d_in[31];

    const int NA = in_sizes[0] / 128;
    const int NB = in_sizes[1] / 64;
    const int E = in_sizes[30] / 2;

    float* hA = (float*)sym(g_hA);
    float* hB = (float*)sym(g_hB);
    float* t1 = (float*)sym(g_t1);
    float* t2 = (float*)sym(g_t2);
    float* t3 = (float*)sym(g_t3);
    float* t4 = (float*)sym(g_t4);
    float* as1_0 = (float*)sym(g_as1_0);
    float* ad1_0 = (float*)sym(g_ad1_0);
    float* as2_0 = (float*)sym(g_as2_0);
    float* ad2_0 = (float*)sym(g_ad2_0);
    float* as1_1 = (float*)sym(g_as1_1);
    float* ad1_1 = (float*)sym(g_ad1_1);
    float* as2_1 = (float*)sym(g_as2_1);
    float* ad2_1 = (float*)sym(g_ad2_1);
    float* wp = (float*)sym(g_wp);
    int* rpAB = (int*)sym(g_rpAB);
    int* rpBA = (int*)sym(g_rpBA);
    int* cur = (int*)sym(g_cur);
    int* deg = (int*)sym(g_deg);
    int* srcAB = (int*)sym(g_srcAB);
    int* srcBA = (int*)sym(g_srcBA);

    float* wpS1_0 = wp + 0 * 512, *wpD1_0 = wp + 1 * 512;
    float* wpS2_0 = wp + 2 * 512, *wpD2_0 = wp + 3 * 512;
    float* wpS1_1 = wp + 4 * 512, *wpD1_1 = wp + 5 * 512;
    float* wpS2_1 = wp + 6 * 512, *wpD2_1 = wp + 7 * 512;

    const int TB = 256;
    const int GT = 512;   // GEMM threads
    const int eb = (E + TB - 1) / TB;
    const int wbA = (NA * 32 + TB - 1) / TB;
    const int wbB = (NB * 32 + TB - 1) / TB;
    const int zbA = (NA + 255) / 256, zbB = (NB + 255) / 256;
    const int PG = 148;

    constexpr int SM128 = gemm_smem_bytes<128>();
    constexpr int SM64 = gemm_smem_bytes<64>();

    static bool s_init = false;
    static cudaStream_t s1, s2, s3;
    static cudaEvent_t eRoot, eWP, eCsrAB, eCsrBA, eSA, eSB, eA0AB, eA0BA, eF1, eF2;
    if (!s_init) {
        cudaStreamCreateWithFlags(&s1, cudaStreamNonBlocking);
        cudaStreamCreateWithFlags(&s2, cudaStreamNonBlocking);
        cudaStreamCreateWithFlags(&s3, cudaStreamNonBlocking);
        cudaEventCreateWithFlags(&eRoot, cudaEventDisableTiming);
        cudaEventCreateWithFlags(&eWP, cudaEventDisableTiming);
        cudaEventCreateWithFlags(&eCsrAB, cudaEventDisableTiming);
        cudaEventCreateWithFlags(&eCsrBA, cudaEventDisableTiming);
        cudaEventCreateWithFlags(&eSA, cudaEventDisableTiming);
        cudaEventCreateWithFlags(&eSB, cudaEventDisableTiming);
        cudaEventCreateWithFlags(&eA0AB, cudaEventDisableTiming);
        cudaEventCreateWithFlags(&eA0BA, cudaEventDisableTiming);
        cudaEventCreateWithFlags(&eF1, cudaEventDisableTiming);
        cudaEventCreateWithFlags(&eF2, cudaEventDisableTiming);
        cudaFuncSetAttribute(gemm_wres<128>, cudaFuncAttributeMaxDynamicSharedMemorySize, SM128);
        cudaFuncSetAttribute(gemm_wres<64>, cudaFuncAttributeMaxDynamicSharedMemorySize, SM64);
        s_init = true;
    }

    float* outA = (float*)d_out;
    float* outB = outA + (size_t)NA * 128;

    // ---- fork ----
    cudaEventRecord(eRoot, 0);
    cudaStreamWaitEvent(s1, eRoot, 0);
    cudaStreamWaitEvent(s2, eRoot, 0);
    cudaStreamWaitEvent(s3, eRoot, 0);

    make_wp_all<<<4, 256, 0, s3>>>(w0ab, as0ab, ad0ab, w0ba, as0ba, ad0ba,
                                   w1ab, as1ab, ad1ab, w1ba, as1ba, ad1ba);
    cudaEventRecord(eWP, s3);

    gemm_wres<128><<<PG, GT, SM128, s1>>>(x_A, pWA, pbA, hA, NA);
    gemm_wres<128><<<PG, GT, SM128, s1>>>(hA, w0ab, nullptr, t1, NA);
    gemm_wres<64><<<PG, GT, SM64, s2>>>(x_B, pWB, pbB, hB, NB);
    gemm_wres<128><<<PG, GT, SM128, s2>>>(hB, w0ba, nullptr, t2, NB);

    zero_int<<<zbB, 256, 0, s3>>>(deg, NB);
    edge_hist<<<eb, TB, 0, s3>>>(ei_AB + E, deg, E);
    exscan_block<<<1, 1024, 0, s3>>>(deg, rpAB, cur, NB);
    edge_fill<<<eb, TB, 0, s3>>>(ei_AB, ei_AB + E, cur, srcAB, E);
    cudaEventRecord(eCsrAB, s3);
    zero_int<<<zbA, 256, 0, s3>>>(deg, NA);
    edge_hist<<<eb, TB, 0, s3>>>(ei_BA + E, deg, E);
    exscan_block<<<1, 1024, 0, s3>>>(deg, rpBA, cur, NA);
    edge_fill<<<eb, TB, 0, s3>>>(ei_BA, ei_BA + E, cur, srcBA, E);
    cudaEventRecord(eCsrBA, s3);

    cudaStreamWaitEvent(s1, eWP, 0);
    node_scores2<4><<<wbA, TB, 0, s1>>>(hA, wpS1_0, wpD2_0, as1_0, ad2_0, NA);
    cudaEventRecord(eSA, s1);
    cudaStreamWaitEvent(s2, eWP, 0);
    node_scores2<4><<<wbB, TB, 0, s2>>>(hB, wpS2_0, wpD1_0, as2_0, ad1_0, NB);
    cudaEventRecord(eSB, s2);

    cudaStreamWaitEvent(s1, eSB, 0);
    cudaStreamWaitEvent(s1, eCsrAB, 0);
    gat_fused<4, true><<<wbB, TB, 0, s1>>>(rpAB, srcAB, as1_0, ad1_0, t1, b0ab,
                                           g0B, bn0B, hB, hB,
                                           wpS2_1, wpD1_1, as2_1, ad1_1, NB);
    cudaEventRecord(eA0AB, s1);
    cudaStreamWaitEvent(s2, eSA, 0);
    cudaStreamWaitEvent(s2, eCsrBA, 0);
    gat_fused<4, true><<<wbA, TB, 0, s2>>>(rpBA, srcBA, as2_0, ad2_0, t2, b0ba,
                                           g0A, bn0A, hA, hA,
                                           wpS1_1, wpD2_1, as1_1, ad2_1, NA);
    cudaEventRecord(eA0BA, s2);

    gemm_wres<128><<<PG, GT, SM128, s1>>>(hB, w1ba, nullptr, t4, NB);
    gemm_wres<128><<<PG, GT, SM128, s2>>>(hA, w1ab, nullptr, t3, NA);

    cudaStreamWaitEvent(s1, eA0BA, 0);
    gat_fused<1, false><<<wbA, TB, 0, s1>>>(rpBA, srcBA, as2_1, ad2_1, t4, b1ba,
                                            g1A, bn1A, hA, outA,
                                            nullptr, nullptr, nullptr, nullptr, NA);
    cudaEventRecord(eF1, s1);
    cudaStreamWaitEvent(s2, eA0AB, 0);
    gat_fused<1, false><<<wbB, TB, 0, s2>>>(rpAB, srcAB, as1_1, ad1_1, t3, b1ab,
                                            g1B, bn1B, hB, outB,
                                            nullptr, nullptr, nullptr, nullptr, NB);
    cudaEventRecord(eF2, s2);

    cudaStreamWaitEvent(0, eF1, 0);
    cudaStreamWaitEvent(0, eF2, 0);
}

// round 16
// speedup vs baseline: 1.1027x; 1.1027x over previous
#include <cuda_runtime.h>
#include <cuda_bf16.h>
#include <cuda_fp16.h>
#include <mma.h>
#include <math.h>
#include <cstdint>

using namespace nvcuda;

// ---------------------------------------------------------------------------
// HeteroGAT encoder.
//   - 6 GEMMs via bf16 split-3 WMMA, W resident in smem (round-8 config:
//     256 threads, 64x64 warp tiles — measured optimum for this HMMA path)
//   - t-buffers (GEMM -> aggregate) stored as fp16: halves gather traffic
//   - CSR-by-dst; fused aggregate + softmax + LN + relu + residual
//   - multi-stream graph parallelism (A-pipe / B-pipe / CSR+wp)
//   - tcgen05 unavailable (harness emits compute_103 PTX, no 'a' features)
// ---------------------------------------------------------------------------

#define NMAX 50176
#define EMAX 500000

__device__ float g_hA[NMAX * 128];
__device__ float g_hB[NMAX * 128];
__device__ __half g_t1[NMAX * 128];
__device__ __half g_t2[NMAX * 128];
__device__ __half g_t3[NMAX * 128];
__device__ __half g_t4[NMAX * 128];
__device__ float g_as1_0[NMAX * 4], g_ad1_0[NMAX * 4];
__device__ float g_as2_0[NMAX * 4], g_ad2_0[NMAX * 4];
__device__ float g_as1_1[NMAX], g_ad1_1[NMAX];
__device__ float g_as2_1[NMAX], g_ad2_1[NMAX];
__device__ float g_wp[8][128 * 4];
__device__ int g_rpAB[NMAX + 1], g_rpBA[NMAX + 1];
__device__ int g_cur[NMAX], g_deg[NMAX];
__device__ int g_srcAB[EMAX], g_srcBA[EMAX];

__device__ __forceinline__ float warpSum(float v) {
#pragma unroll
    for (int o = 16; o > 0; o >>= 1) v += __shfl_xor_sync(0xffffffffu, v, o);
    return v;
}
__device__ __forceinline__ float warpMax(float v) {
#pragma unroll
    for (int o = 16; o > 0; o >>= 1) v = fmaxf(v, __shfl_xor_sync(0xffffffffu, v, o));
    return v;
}

// ---------------------------------------------------------------------------
// bf16 split-3 WMMA GEMM, persistent CTAs, W resident in smem, 256 threads.
// out[M,128] = X[M,K] @ W[K,128] (+ bias). K in {64,128}. out NMAX-padded.
// HOUT: emit __half output (for aggregate t-buffers) via warp-private stage.
// ---------------------------------------------------------------------------
template <int K, bool HOUT>
__global__ __launch_bounds__(256) void gemm_wres(
    const float* __restrict__ X, const float* __restrict__ W,
    const float* __restrict__ bias, void* __restrict__ outv, int M) {
    constexpr int WLD = 136;
    constexpr int XLD = K + 8;
    constexpr int SPR = K / 4;

    extern __shared__ __nv_bfloat16 smx[];
    __nv_bfloat16* Whi = smx;
    __nv_bfloat16* Wlo = Whi + K * WLD;
    __nv_bfloat16* Xhi = Wlo + K * WLD;
    __nv_bfloat16* Xlo = Xhi + 128 * XLD;
    __shared__ float Bs[16][WLD];
    __shared__ float stg[8][16][20];   // warp-private epilogue stage (HOUT)

    const int tid = threadIdx.x;
    const int wid = tid >> 5;
    const int lane = tid & 31;
    const int warp_row = (wid >> 1) * 32;
    const int warp_col = (wid & 1) * 64;

    if (bias) {
#pragma unroll
        for (int i = tid; i < 16 * 128; i += 256) Bs[i >> 7][i & 127] = bias[i & 127];
    }
    for (int idx = tid; idx < K * 32; idx += 256) {
        int r = idx >> 5;
        int c4 = (idx & 31) * 4;
        float4 v = *(const float4*)&W[(size_t)r * 128 + c4];
        float vv[4] = {v.x, v.y, v.z, v.w};
        __nv_bfloat16 h[4], l[4];
#pragma unroll
        for (int q = 0; q < 4; q++) {
            h[q] = __float2bfloat16(vv[q]);
            l[q] = __float2bfloat16(vv[q] - __bfloat162float(h[q]));
        }
        *(__nv_bfloat162*)&Whi[r * WLD + c4] = __nv_bfloat162{h[0], h[1]};
        *(__nv_bfloat162*)&Whi[r * WLD + c4 + 2] = __nv_bfloat162{h[2], h[3]};
        *(__nv_bfloat162*)&Wlo[r * WLD + c4] = __nv_bfloat162{l[0], l[1]};
        *(__nv_bfloat162*)&Wlo[r * WLD + c4 + 2] = __nv_bfloat162{l[2], l[3]};
    }
    __syncthreads();

    const int nTiles = (M + 127) >> 7;
    for (int t = blockIdx.x; t < nTiles; t += gridDim.x) {
        const int block_row = t * 128;
#pragma unroll
        for (int p = 0; p < 128 * SPR / 256; p++) {
            int idx = tid + p * 256;
            int r = idx / SPR;
            int c4 = (idx % SPR) * 4;
            int gr = block_row + r;
            float4 v = make_float4(0.f, 0.f, 0.f, 0.f);
            if (gr < M) v = *(const float4*)&X[(size_t)gr * K + c4];
            float vv[4] = {v.x, v.y, v.z, v.w};
            __nv_bfloat16 h[4], l[4];
#pragma unroll
            for (int q = 0; q < 4; q++) {
                h[q] = __float2bfloat16(vv[q]);
                l[q] = __float2bfloat16(vv[q] - __bfloat162float(h[q]));
            }
            *(__nv_bfloat162*)&Xhi[r * XLD + c4] = __nv_bfloat162{h[0], h[1]};
            *(__nv_bfloat162*)&Xhi[r * XLD + c4 + 2] = __nv_bfloat162{h[2], h[3]};
            *(__nv_bfloat162*)&Xlo[r * XLD + c4] = __nv_bfloat162{l[0], l[1]};
            *(__nv_bfloat162*)&Xlo[r * XLD + c4 + 2] = __nv_bfloat162{l[2], l[3]};
        }
        __syncthreads();

        wmma::fragment<wmma::accumulator, 16, 16, 16, float> acc[2][4];
#pragma unroll
        for (int i = 0; i < 2; i++)
#pragma unroll
            for (int j = 0; j < 4; j++) {
                if (bias)
                    wmma::load_matrix_sync(acc[i][j], &Bs[0][warp_col + j * 16], WLD,
                                           wmma::mem_row_major);
                else
                    wmma::fill_fragment(acc[i][j], 0.f);
            }

#pragma unroll 2
        for (int ks = 0; ks < K; ks += 16) {
            wmma::fragment<wmma::matrix_a, 16, 16, 16, __nv_bfloat16, wmma::row_major> ahi[2], alo[2];
            wmma::fragment<wmma::matrix_b, 16, 16, 16, __nv_bfloat16, wmma::row_major> bhi[4], blo[4];
#pragma unroll
            for (int i = 0; i < 2; i++) {
                wmma::load_matrix_sync(ahi[i], &Xhi[(warp_row + i * 16) * XLD + ks], XLD);
                wmma::load_matrix_sync(alo[i], &Xlo[(warp_row + i * 16) * XLD + ks], XLD);
            }
#pragma unroll
            for (int j = 0; j < 4; j++) {
                wmma::load_matrix_sync(bhi[j], &Whi[ks * WLD + warp_col + j * 16], WLD);
                wmma::load_matrix_sync(blo[j], &Wlo[ks * WLD + warp_col + j * 16], WLD);
            }
#pragma unroll
            for (int i = 0; i < 2; i++)
#pragma unroll
                for (int j = 0; j < 4; j++) {
                    wmma::mma_sync(acc[i][j], ahi[i], blo[j], acc[i][j]);
                    wmma::mma_sync(acc[i][j], alo[i], bhi[j], acc[i][j]);
                    wmma::mma_sync(acc[i][j], ahi[i], bhi[j], acc[i][j]);
                }
        }

        if (!HOUT) {
            float* out = (float*)outv;
#pragma unroll
            for (int i = 0; i < 2; i++)
#pragma unroll
                for (int j = 0; j < 4; j++) {
                    size_t off = (size_t)(block_row + warp_row + i * 16) * 128 + warp_col + j * 16;
                    wmma::store_matrix_sync(&out[off], acc[i][j], 128, wmma::mem_row_major);
                }
        } else {
            __half* out = (__half*)outv;
            const int r = lane >> 1;
            const int c0 = (lane & 1) * 8;
#pragma unroll
            for (int i = 0; i < 2; i++)
#pragma unroll
                for (int j = 0; j < 4; j++) {
                    wmma::store_matrix_sync(&stg[wid][0][0], acc[i][j], 20,
                                            wmma::mem_row_major);
                    __syncwarp();
                    __half2 hp[4];
#pragma unroll
                    for (int q = 0; q < 4; q++) {
                        float a = stg[wid][r][c0 + 2 * q];
                        float b = stg[wid][r][c0 + 2 * q + 1];
                        hp[q] = __floats2half2_rn(a, b);
                    }
                    size_t off = (size_t)(block_row + warp_row + i * 16 + r) * 128 +
                                 warp_col + j * 16 + c0;
                    uint4 pk;
                    pk.x = *reinterpret_cast<unsigned int*>(&hp[0]);
                    pk.y = *reinterpret_cast<unsigned int*>(&hp[1]);
                    pk.z = *reinterpret_cast<unsigned int*>(&hp[2]);
                    pk.w = *reinterpret_cast<unsigned int*>(&hp[3]);
                    *reinterpret_cast<uint4*>(&out[off]) = pk;
                    __syncwarp();
                }
        }
        __syncthreads();
    }
}

template <int K>
constexpr int gemm_smem_bytes() {
    return (2 * K * 136 + 2 * 128 * (K + 8)) * (int)sizeof(__nv_bfloat16);
}

// ---------------------------------------------------------------------------
__global__ void make_wp_all(
    const float* __restrict__ w0ab, const float* __restrict__ as0ab, const float* __restrict__ ad0ab,
    const float* __restrict__ w0ba, const float* __restrict__ as0ba, const float* __restrict__ ad0ba,
    const float* __restrict__ w1ab, const float* __restrict__ as1ab, const float* __restrict__ ad1ab,
    const float* __restrict__ w1ba, const float* __restrict__ as1ba, const float* __restrict__ ad1ba) {
    __shared__ float Ws[64][129];
    int cfg = blockIdx.x;
    const float* W = cfg == 0 ? w0ab : cfg == 1 ? w0ba : cfg == 2 ? w1ab : w1ba;
    const float* avs = cfg == 0 ? as0ab : cfg == 1 ? as0ba : cfg == 2 ? as1ab : as1ba;
    const float* avd = cfg == 0 ? ad0ab : cfg == 1 ? ad0ba : cfg == 2 ? ad1ab : ad1ba;
    const int H = (cfg < 2) ? 4 : 1;
    const int D = 128 / H;
    float* wpS = g_wp[cfg * 2];
    float* wpD = g_wp[cfg * 2 + 1];

    int tid = threadIdx.x;
    float ss[4] = {0.f, 0.f, 0.f, 0.f}, sd[4] = {0.f, 0.f, 0.f, 0.f};
    for (int chunk = 0; chunk < 2; chunk++) {
        int r0 = chunk * 64;
        for (int i = tid; i < 64 * 128; i += 256)
            Ws[i >> 7][i & 127] = W[(size_t)(r0 + (i >> 7)) * 128 + (i & 127)];
        __syncthreads();
        int k = tid;
        if (k < 128 && k >= r0 && k < r0 + 64) {
            for (int h = 0; h < H; h++) {
                float a = 0.f, b = 0.f;
                for (int d = 0; d < D; d++) {
                    float w = Ws[k - r0][h * D + d];
                    a += w * avs[h * D + d];
                    b += w * avd[h * D + d];
                }
                ss[h] = a; sd[h] = b;
            }
        }
        __syncthreads();
    }
    if (tid < 128)
        for (int h = 0; h < H; h++) { wpS[tid * H + h] = ss[h]; wpD[tid * H + h] = sd[h]; }
}

// ---------------------------------------------------------------------------
template <int H>
__global__ void node_scores2(const float* __restrict__ X, const float* __restrict__ wpS,
                             const float* __restrict__ wpD, float* __restrict__ outS,
                             float* __restrict__ outD, int N) {
    int w = (blockIdx.x * blockDim.x + threadIdx.x) >> 5;
    int lane = threadIdx.x & 31;
    if (w >= N) return;
    const float* xr = X + (size_t)w * 128;
    float accS[H], accD[H];
#pragma unroll
    for (int h = 0; h < H; h++) { accS[h] = 0.f; accD[h] = 0.f; }
#pragma unroll
    for (int kk = 0; kk < 4; kk++) {
        int k = lane + kk * 32;
        float x = xr[k];
#pragma unroll
        for (int h = 0; h < H; h++) {
            accS[h] += x * wpS[k * H + h];
            accD[h] += x * wpD[k * H + h];
        }
    }
#pragma unroll
    for (int h = 0; h < H; h++) { accS[h] = warpSum(accS[h]); accD[h] = warpSum(accD[h]); }
    if (lane == 0) {
#pragma unroll
        for (int h = 0; h < H; h++) { outS[w * H + h] = accS[h]; outD[w * H + h] = accD[h]; }
    }
}

// ---------------------------------------------------------------------------
__global__ void edge_hist(const int* __restrict__ dst, int* __restrict__ deg, int E) {
    int e = blockIdx.x * blockDim.x + threadIdx.x;
    if (e < E) atomicAdd(&deg[dst[e]], 1);
}
__global__ void edge_fill(const int* __restrict__ src, const int* __restrict__ dst,
                          int* __restrict__ cursor, int* __restrict__ col, int E) {
    int e = blockIdx.x * blockDim.x + threadIdx.x;
    if (e < E) {
        int p = atomicAdd(&cursor[dst[e]], 1);
        col[p] = src[e];
    }
}
__global__ __launch_bounds__(1024) void exscan_block(
    const int* __restrict__ deg, int* __restrict__ rowptr, int* __restrict__ cursor, int N) {
    __shared__ int sums[1024];
    int t = threadIdx.x;
    int chunk = (N + 1023) / 1024;
    int b0 = t * chunk;
    int b1 = min(b0 + chunk, N);
    int s = 0;
    for (int i = b0; i < b1; i++) s += deg[i];
    sums[t] = s;
    __syncthreads();
    for (int off = 1; off < 1024; off <<= 1) {
        int v = (t >= off) ? sums[t - off] : 0;
        __syncthreads();
        sums[t] += v;
        __syncthreads();
    }
    int run = (t == 0) ? 0 : sums[t - 1];
    for (int i = b0; i < b1; i++) {
        rowptr[i] = run;
        cursor[i] = run;
        run += deg[i];
    }
    if (t == 1023) rowptr[N] = run;
}
__global__ void zero_int(int* __restrict__ p, int n) {
    int i = blockIdx.x * blockDim.x + threadIdx.x;
    if (i < n) p[i] = 0;
}

// ---------------------------------------------------------------------------
// fused GAT aggregate + softmax + bias + LN + relu + residual (+ next scores)
// tS is fp16: 256B gathered rows (halved traffic vs fp32)
// ---------------------------------------------------------------------------
__device__ __forceinline__ float4 ldt_half4(const __half* p) {
    uint2 u = *(const uint2*)p;
    __half2 h0 = *reinterpret_cast<__half2*>(&u.x);
    __half2 h1 = *reinterpret_cast<__half2*>(&u.y);
    float2 f0 = __half22float2(h0);
    float2 f1 = __half22float2(h1);
    return make_float4(f0.x, f0.y, f1.x, f1.y);
}

template <int H, bool SC>
__global__ __launch_bounds__(256) void gat_fused(
    const int* __restrict__ rowptr, const int* __restrict__ srcs,
    const float* __restrict__ a_s, const float* __restrict__ a_d,
    const __half* __restrict__ tS, const float* __restrict__ gbias,
    const float* __restrict__ gamma, const float* __restrict__ beta,
    const float* __restrict__ hprev, float* __restrict__ hout,
    const float* __restrict__ wpSn, const float* __restrict__ wpDn,
    float* __restrict__ outSn, float* __restrict__ outDn, int Ndst) {
    const int D = 128 / H;
    const int CAP = 64;
    __shared__ float s_ex[8][CAP * H];
    __shared__ int s_src[8][CAP];

    int wid = (blockIdx.x * blockDim.x + threadIdx.x) >> 5;
    int w = threadIdx.x >> 5;
    int lane = threadIdx.x & 31;
    if (wid >= Ndst) return;
    int start = rowptr[wid];
    int end = rowptr[wid + 1];
    int deg = end - start;

    float adh[H];
#pragma unroll
    for (int h = 0; h < H; h++) adh[h] = a_d[wid * H + h];

    const int hh = (lane * 4) / D;
    float4 acc = make_float4(0.f, 0.f, 0.f, 0.f);

    if (deg <= CAP) {
        float sc[2][H];
        int nIt = (deg + 31) >> 5;
        float mx[H];
#pragma unroll
        for (int h = 0; h < H; h++) mx[h] = -3.0e38f;
#pragma unroll
        for (int i = 0; i < 2; i++) {
            int j = lane + i * 32;
            if (i < nIt && j < deg) {
                int s = srcs[start + j];
                s_src[w][j] = s;
                float av[H];
                if (H == 4) {
                    float4 a4 = *(const float4*)(a_s + (size_t)s * 4);
                    av[0] = a4.x; av[1] = a4.y; av[2] = a4.z; av[3] = a4.w;
                } else {
                    av[0] = a_s[s];
                }
#pragma unroll
                for (int h = 0; h < H; h++) {
                    float v = av[h] + adh[h];
                    v = v > 0.f ? v : 0.2f * v;
                    sc[i][h] = v;
                    mx[h] = fmaxf(mx[h], v);
                }
            }
        }
#pragma unroll
        for (int h = 0; h < H; h++) mx[h] = warpMax(mx[h]);

        float sm[H];
#pragma unroll
        for (int h = 0; h < H; h++) sm[h] = 0.f;
#pragma unroll
        for (int i = 0; i < 2; i++) {
            int j = lane + i * 32;
            if (i < nIt && j < deg) {
#pragma unroll
                for (int h = 0; h < H; h++) {
                    float ex = __expf(sc[i][h] - mx[h]);
                    sm[h] += ex;
                    s_ex[w][j * H + h] = ex;
                }
            }
        }
#pragma unroll
        for (int h = 0; h < H; h++) sm[h] = warpSum(sm[h]);
        float invh;
        if (H == 1) invh = 1.f / (sm[0] + 1e-16f);
        else invh = 1.f / ((hh == 0 ? sm[0] : hh == 1 ? sm[1] : hh == 2 ? sm[2] : sm[3]) + 1e-16f);

        __syncwarp();
        int e = 0;
        for (; e + 4 <= deg; e += 4) {
            float ex0 = s_ex[w][(e + 0) * H + hh];
            float ex1 = s_ex[w][(e + 1) * H + hh];
            float ex2 = s_ex[w][(e + 2) * H + hh];
            float ex3 = s_ex[w][(e + 3) * H + hh];
            int s0 = s_src[w][e + 0], s1 = s_src[w][e + 1];
            int s2 = s_src[w][e + 2], s3 = s_src[w][e + 3];
            float4 v0 = ldt_half4(tS + (size_t)s0 * 128 + lane * 4);
            float4 v1 = ldt_half4(tS + (size_t)s1 * 128 + lane * 4);
            float4 v2 = ldt_half4(tS + (size_t)s2 * 128 + lane * 4);
            float4 v3 = ldt_half4(tS + (size_t)s3 * 128 + lane * 4);
            acc.x += v0.x * ex0 + v1.x * ex1 + v2.x * ex2 + v3.x * ex3;
            acc.y += v0.y * ex0 + v1.y * ex1 + v2.y * ex2 + v3.y * ex3;
            acc.z += v0.z * ex0 + v1.z * ex1 + v2.z * ex2 + v3.z * ex3;
            acc.w += v0.w * ex0 + v1.w * ex1 + v2.w * ex2 + v3.w * ex3;
        }
        for (; e < deg; e++) {
            float ex = s_ex[w][e * H + hh];
            int s = s_src[w][e];
            float4 v = ldt_half4(tS + (size_t)s * 128 + lane * 4);
            acc.x += v.x * ex; acc.y += v.y * ex; acc.z += v.z * ex; acc.w += v.w * ex;
        }
        acc.x *= invh; acc.y *= invh; acc.z *= invh; acc.w *= invh;
    } else {
        float mx[H];
#pragma unroll
        for (int h = 0; h < H; h++) mx[h] = -3.0e38f;
        for (int e = start + lane; e < end; e += 32) {
            int s = srcs[e];
#pragma unroll
            for (int h = 0; h < H; h++) {
                float v = a_s[s * H + h] + adh[h];
                v = v > 0.f ? v : 0.2f * v;
                mx[h] = fmaxf(mx[h], v);
            }
        }
#pragma unroll
        for (int h = 0; h < H; h++) mx[h] = warpMax(mx[h]);
        float sm[H];
#pragma unroll
        for (int h = 0; h < H; h++) sm[h] = 0.f;
        for (int e = start + lane; e < end; e += 32) {
            int s = srcs[e];
#pragma unroll
            for (int h = 0; h < H; h++) {
                float v = a_s[s * H + h] + adh[h];
                v = v > 0.f ? v : 0.2f * v;
                sm[h] += __expf(v - mx[h]);
            }
        }
#pragma unroll
        for (int h = 0; h < H; h++) sm[h] = warpSum(sm[h]);
        float invh;
        if (H == 1) invh = 1.f / (sm[0] + 1e-16f);
        else invh = 1.f / ((hh == 0 ? sm[0] : hh == 1 ? sm[1] : hh == 2 ? sm[2] : sm[3]) + 1e-16f);
        float mxh = (H == 1) ? mx[0] : (hh == 0 ? mx[0] : hh == 1 ? mx[1] : hh == 2 ? mx[2] : mx[3]);
        float adhh = (H == 1) ? adh[0] : (hh == 0 ? adh[0] : hh == 1 ? adh[1] : hh == 2 ? adh[2] : adh[3]);
        for (int e = start; e < end; e++) {
            int s = srcs[e];
            float v = a_s[s * H + hh] + adhh;
            v = v > 0.f ? v : 0.2f * v;
            float ex = __expf(v - mxh);
            float4 t = ldt_half4(tS + (size_t)s * 128 + lane * 4);
            acc.x += t.x * ex; acc.y += t.y * ex; acc.z += t.z * ex; acc.w += t.w * ex;
        }
        acc.x *= invh; acc.y *= invh; acc.z *= invh; acc.w *= invh;
    }

    size_t rbase = (size_t)wid * 128 + lane * 4;
    float4 bb = *(const float4*)(gbias + lane * 4);
    acc.x += bb.x; acc.y += bb.y; acc.z += bb.z; acc.w += bb.w;
    float mu = warpSum(acc.x + acc.y + acc.z + acc.w) * (1.f / 128.f);
    float dx = acc.x - mu, dy = acc.y - mu, dz = acc.z - mu, dw = acc.w - mu;
    float var = warpSum(dx * dx + dy * dy + dz * dz + dw * dw) * (1.f / 128.f);
    float r = rsqrtf(var + 1e-5f);
    float4 gg = *(const float4*)(gamma + lane * 4);
    float4 be = *(const float4*)(beta + lane * 4);
    float4 hp = *(const float4*)(hprev + rbase);
    float4 o;
    o.x = fmaxf(0.f, dx * r * gg.x + be.x) + hp.x;
    o.y = fmaxf(0.f, dy * r * gg.y + be.y) + hp.y;
    o.z = fmaxf(0.f, dz * r * gg.z + be.z) + hp.z;
    o.w = fmaxf(0.f, dw * r * gg.w + be.w) + hp.w;
    *(float4*)(hout + rbase) = o;

    if (SC) {
        float4 ws = *(const float4*)(wpSn + lane * 4);
        float4 wd = *(const float4*)(wpDn + lane * 4);
        float sS = o.x * ws.x + o.y * ws.y + o.z * ws.z + o.w * ws.w;
        float sD = o.x * wd.x + o.y * wd.y + o.z * wd.z + o.w * wd.w;
        sS = warpSum(sS);
        sD = warpSum(sD);
        if (lane == 0) { outSn[wid] = sS; outDn[wid] = sD; }
    }
}

// ---------------------------------------------------------------------------
static inline void* sym(const void* s) {
    void* p = nullptr;
    cudaGetSymbolAddress(&p, s);
    return p;
}

extern "C" void kernel_launch(void* const* d_in, const int* in_sizes, int n_in,
                              void* d_out, int out_size) {
    const float* x_A = (const float*)d_in[0];
    const float* x_B = (const float*)d_in[1];
    const float* pWA = (const float*)d_in[2];
    const float* pbA = (const float*)d_in[3];
    const float* pWB = (const float*)d_in[4];
    const float* pbB = (const float*)d_in[5];
    const float* w0ab = (const float*)d_in[6];
    const float* as0ab = (const float*)d_in[7];
    const float* ad0ab = (const float*)d_in[8];
    const float* b0ab = (const float*)d_in[9];
    const float* w0ba = (const float*)d_in[10];
    const float* as0ba = (const float*)d_in[11];
    const float* ad0ba = (const float*)d_in[12];
    const float* b0ba = (const float*)d_in[13];
    const float* w1ab = (const float*)d_in[14];
    const float* as1ab = (const float*)d_in[15];
    const float* ad1ab = (const float*)d_in[16];
    const float* b1ab = (const float*)d_in[17];
    const float* w1ba = (const float*)d_in[18];
    const float* as1ba = (const float*)d_in[19];
    const float* ad1ba = (const float*)d_in[20];
    const float* b1ba = (const float*)d_in[21];
    const float* g0A = (const float*)d_in[22];
    const float* bn0A = (const float*)d_in[23];
    const float* g0B = (const float*)d_in[24];
    const float* bn0B = (const float*)d_in[25];
    const float* g1A = (const float*)d_in[26];
    const float* bn1A = (const float*)d_in[27];
    const float* g1B = (const float*)d_in[28];
    const float* bn1B = (const float*)d_in[29];
    const int* ei_AB = (const int*)d_in[30];
    const int* ei_BA = (const int*)d_in[31];

    const int NA = in_sizes[0] / 128;
    const int NB = in_sizes[1] / 64;
    const int E = in_sizes[30] / 2;

    float* hA = (float*)sym(g_hA);
    float* hB = (float*)sym(g_hB);
    __half* t1 = (__half*)sym(g_t1);
    __half* t2 = (__half*)sym(g_t2);
    __half* t3 = (__half*)sym(g_t3);
    __half* t4 = (__half*)sym(g_t4);
    float* as1_0 = (float*)sym(g_as1_0);
    float* ad1_0 = (float*)sym(g_ad1_0);
    float* as2_0 = (float*)sym(g_as2_0);
    float* ad2_0 = (float*)sym(g_ad2_0);
    float* as1_1 = (float*)sym(g_as1_1);
    float* ad1_1 = (float*)sym(g_ad1_1);
    float* as2_1 = (float*)sym(g_as2_1);
    float* ad2_1 = (float*)sym(g_ad2_1);
    float* wp = (float*)sym(g_wp);
    int* rpAB = (int*)sym(g_rpAB);
    int* rpBA = (int*)sym(g_rpBA);
    int* cur = (int*)sym(g_cur);
    int* deg = (int*)sym(g_deg);
    int* srcAB = (int*)sym(g_srcAB);
    int* srcBA = (int*)sym(g_srcBA);

    float* wpS1_0 = wp + 0 * 512, *wpD1_0 = wp + 1 * 512;
    float* wpS2_0 = wp + 2 * 512, *wpD2_0 = wp + 3 * 512;
    float* wpS1_1 = wp + 4 * 512, *wpD1_1 = wp + 5 * 512;
    float* wpS2_1 = wp + 6 * 512, *wpD2_1 = wp + 7 * 512;

    const int TB = 256;
    const int eb = (E + TB - 1) / TB;
    const int wbA = (NA * 32 + TB - 1) / TB;
    const int wbB = (NB * 32 + TB - 1) / TB;
    const int zbA = (NA + 255) / 256, zbB = (NB + 255) / 256;
    const int PG = 148;

    constexpr int SM128 = gemm_smem_bytes<128>();
    constexpr int SM64 = gemm_smem_bytes<64>();

    static bool s_init = false;
    static cudaStream_t s1, s2, s3;
    static cudaEvent_t eRoot, eWP, eCsrAB, eCsrBA, eSA, eSB, eA0AB, eA0BA, eF1, eF2;
    if (!s_init) {
        cudaStreamCreateWithFlags(&s1, cudaStreamNonBlocking);
        cudaStreamCreateWithFlags(&s2, cudaStreamNonBlocking);
        cudaStreamCreateWithFlags(&s3, cudaStreamNonBlocking);
        cudaEventCreateWithFlags(&eRoot, cudaEventDisableTiming);
        cudaEventCreateWithFlags(&eWP, cudaEventDisableTiming);
        cudaEventCreateWithFlags(&eCsrAB, cudaEventDisableTiming);
        cudaEventCreateWithFlags(&eCsrBA, cudaEventDisableTiming);
        cudaEventCreateWithFlags(&eSA, cudaEventDisableTiming);
        cudaEventCreateWithFlags(&eSB, cudaEventDisableTiming);
        cudaEventCreateWithFlags(&eA0AB, cudaEventDisableTiming);
        cudaEventCreateWithFlags(&eA0BA, cudaEventDisableTiming);
        cudaEventCreateWithFlags(&eF1, cudaEventDisableTiming);
        cudaEventCreateWithFlags(&eF2, cudaEventDisableTiming);
        cudaFuncSetAttribute(gemm_wres<128, false>, cudaFuncAttributeMaxDynamicSharedMemorySize, SM128);
        cudaFuncSetAttribute(gemm_wres<128, true>, cudaFuncAttributeMaxDynamicSharedMemorySize, SM128);
        cudaFuncSetAttribute(gemm_wres<64, false>, cudaFuncAttributeMaxDynamicSharedMemorySize, SM64);
        s_init = true;
    }

    float* outA = (float*)d_out;
    float* outB = outA + (size_t)NA * 128;

    // ---- fork ----
    cudaEventRecord(eRoot, 0);
    cudaStreamWaitEvent(s1, eRoot, 0);
    cudaStreamWaitEvent(s2, eRoot, 0);
    cudaStreamWaitEvent(s3, eRoot, 0);

    make_wp_all<<<4, 256, 0, s3>>>(w0ab, as0ab, ad0ab, w0ba, as0ba, ad0ba,
                                   w1ab, as1ab, ad1ab, w1ba, as1ba, ad1ba);
    cudaEventRecord(eWP, s3);

    gemm_wres<128, false><<<PG, TB, SM128, s1>>>(x_A, pWA, pbA, hA, NA);
    gemm_wres<128, true><<<PG, TB, SM128, s1>>>(hA, w0ab, nullptr, t1, NA);
    gemm_wres<64, false><<<PG, TB, SM64, s2>>>(x_B, pWB, pbB, hB, NB);
    gemm_wres<128, true><<<PG, TB, SM128, s2>>>(hB, w0ba, nullptr, t2, NB);

    zero_int<<<zbB, 256, 0, s3>>>(deg, NB);
    edge_hist<<<eb, TB, 0, s3>>>(ei_AB + E, deg, E);
    exscan_block<<<1, 1024, 0, s3>>>(deg, rpAB, cur, NB);
    edge_fill<<<eb, TB, 0, s3>>>(ei_AB, ei_AB + E, cur, srcAB, E);
    cudaEventRecord(eCsrAB, s3);
    zero_int<<<zbA, 256, 0, s3>>>(deg, NA);
    edge_hist<<<eb, TB, 0, s3>>>(ei_BA + E, deg, E);
    exscan_block<<<1, 1024, 0, s3>>>(deg, rpBA, cur, NA);
    edge_fill<<<eb, TB, 0, s3>>>(ei_BA, ei_BA + E, cur, srcBA, E);
    cudaEventRecord(eCsrBA, s3);

    cudaStreamWaitEvent(s1, eWP, 0);
    node_scores2<4><<<wbA, TB, 0, s1>>>(hA, wpS1_0, wpD2_0, as1_0, ad2_0, NA);
    cudaEventRecord(eSA, s1);
    cudaStreamWaitEvent(s2, eWP, 0);
    node_scores2<4><<<wbB, TB, 0, s2>>>(hB, wpS2_0, wpD1_0, as2_0, ad1_0, NB);
    cudaEventRecord(eSB, s2);

    cudaStreamWaitEvent(s1, eSB, 0);
    cudaStreamWaitEvent(s1, eCsrAB, 0);
    gat_fused<4, true><<<wbB, TB, 0, s1>>>(rpAB, srcAB, as1_0, ad1_0, t1, b0ab,
                                           g0B, bn0B, hB, hB,
                                           wpS2_1, wpD1_1, as2_1, ad1_1, NB);
    cudaEventRecord(eA0AB, s1);
    cudaStreamWaitEvent(s2, eSA, 0);
    cudaStreamWaitEvent(s2, eCsrBA, 0);
    gat_fused<4, true><<<wbA, TB, 0, s2>>>(rpBA, srcBA, as2_0, ad2_0, t2, b0ba,
                                           g0A, bn0A, hA, hA,
                                           wpS1_1, wpD2_1, as1_1, ad2_1, NA);
    cudaEventRecord(eA0BA, s2);

    gemm_wres<128, true><<<PG, TB, SM128, s1>>>(hB, w1ba, nullptr, t4, NB);
    gemm_wres<128, true><<<PG, TB, SM128, s2>>>(hA, w1ab, nullptr, t3, NA);

    cudaStreamWaitEvent(s1, eA0BA, 0);
    gat_fused<1, false><<<wbA, TB, 0, s1>>>(rpBA, srcBA, as2_1, ad2_1, t4, b1ba,
                                            g1A, bn1A, hA, outA,
                                            nullptr, nullptr, nullptr, nullptr, NA);
    cudaEventRecord(eF1, s1);
    cudaStreamWaitEvent(s2, eA0AB, 0);
    gat_fused<1, false><<<wbB, TB, 0, s2>>>(rpAB, srcAB, as1_1, ad1_1, t3, b1ab,
                                            g1B, bn1B, hB, outB,
                                            nullptr, nullptr, nullptr, nullptr, NB);
    cudaEventRecord(eF2, s2);

    cudaStreamWaitEvent(0, eF1, 0);
    cudaStreamWaitEvent(0, eF2, 0);
}

// round 17
// speedup vs baseline: 1.1668x; 1.0581x over previous
#include <cuda_runtime.h>
#include <cuda_bf16.h>
#include <cuda_fp16.h>
#include <mma.h>
#include <math.h>
#include <cstdint>

using namespace nvcuda;

// ---------------------------------------------------------------------------
// HeteroGAT encoder.
//   - 6 GEMMs via bf16 split-3 WMMA, W resident in smem (round-8 config)
//   - fp16 t-buffers; CSR-by-dst; fused aggregate+softmax+LN+relu+residual
//   - CONSOLIDATED GRAPH: both directions merged per kernel where possible
//     (14 kernels / 7 events vs 25/10) to cut graph-node overhead
// ---------------------------------------------------------------------------

#define NMAX 50176
#define EMAX 500000

__device__ float g_hA[NMAX * 128];
__device__ float g_hB[NMAX * 128];
__device__ __half g_t1[NMAX * 128];
__device__ __half g_t2[NMAX * 128];
__device__ __half g_t3[NMAX * 128];
__device__ __half g_t4[NMAX * 128];
__device__ float g_as1_0[NMAX * 4], g_ad1_0[NMAX * 4];
__device__ float g_as2_0[NMAX * 4], g_ad2_0[NMAX * 4];
__device__ float g_as1_1[NMAX], g_ad1_1[NMAX];
__device__ float g_as2_1[NMAX], g_ad2_1[NMAX];
__device__ float g_wp[8][128 * 4];
__device__ int g_rpAB[NMAX + 1], g_rpBA[NMAX + 1];
__device__ int g_curAB[NMAX], g_curBA[NMAX];
__device__ int g_degAB[NMAX], g_degBA[NMAX];
__device__ int g_srcAB[EMAX], g_srcBA[EMAX];

__device__ __forceinline__ float warpSum(float v) {
#pragma unroll
    for (int o = 16; o > 0; o >>= 1) v += __shfl_xor_sync(0xffffffffu, v, o);
    return v;
}
__device__ __forceinline__ float warpMax(float v) {
#pragma unroll
    for (int o = 16; o > 0; o >>= 1) v = fmaxf(v, __shfl_xor_sync(0xffffffffu, v, o));
    return v;
}

// ---------------------------------------------------------------------------
// bf16 split-3 WMMA GEMM (round-8 proven config; HOUT = fp16 output)
// ---------------------------------------------------------------------------
template <int K, bool HOUT>
__global__ __launch_bounds__(256) void gemm_wres(
    const float* __restrict__ X, const float* __restrict__ W,
    const float* __restrict__ bias, void* __restrict__ outv, int M) {
    constexpr int WLD = 136;
    constexpr int XLD = K + 8;
    constexpr int SPR = K / 4;

    extern __shared__ __nv_bfloat16 smx[];
    __nv_bfloat16* Whi = smx;
    __nv_bfloat16* Wlo = Whi + K * WLD;
    __nv_bfloat16* Xhi = Wlo + K * WLD;
    __nv_bfloat16* Xlo = Xhi + 128 * XLD;
    __shared__ float Bs[16][WLD];
    __shared__ float stg[8][16][20];

    const int tid = threadIdx.x;
    const int wid = tid >> 5;
    const int lane = tid & 31;
    const int warp_row = (wid >> 1) * 32;
    const int warp_col = (wid & 1) * 64;

    if (bias) {
#pragma unroll
        for (int i = tid; i < 16 * 128; i += 256) Bs[i >> 7][i & 127] = bias[i & 127];
    }
    for (int idx = tid; idx < K * 32; idx += 256) {
        int r = idx >> 5;
        int c4 = (idx & 31) * 4;
        float4 v = *(const float4*)&W[(size_t)r * 128 + c4];
        float vv[4] = {v.x, v.y, v.z, v.w};
        __nv_bfloat16 h[4], l[4];
#pragma unroll
        for (int q = 0; q < 4; q++) {
            h[q] = __float2bfloat16(vv[q]);
            l[q] = __float2bfloat16(vv[q] - __bfloat162float(h[q]));
        }
        *(__nv_bfloat162*)&Whi[r * WLD + c4] = __nv_bfloat162{h[0], h[1]};
        *(__nv_bfloat162*)&Whi[r * WLD + c4 + 2] = __nv_bfloat162{h[2], h[3]};
        *(__nv_bfloat162*)&Wlo[r * WLD + c4] = __nv_bfloat162{l[0], l[1]};
        *(__nv_bfloat162*)&Wlo[r * WLD + c4 + 2] = __nv_bfloat162{l[2], l[3]};
    }
    __syncthreads();

    const int nTiles = (M + 127) >> 7;
    for (int t = blockIdx.x; t < nTiles; t += gridDim.x) {
        const int block_row = t * 128;
#pragma unroll
        for (int p = 0; p < 128 * SPR / 256; p++) {
            int idx = tid + p * 256;
            int r = idx / SPR;
            int c4 = (idx % SPR) * 4;
            int gr = block_row + r;
            float4 v = make_float4(0.f, 0.f, 0.f, 0.f);
            if (gr < M) v = *(const float4*)&X[(size_t)gr * K + c4];
            float vv[4] = {v.x, v.y, v.z, v.w};
            __nv_bfloat16 h[4], l[4];
#pragma unroll
            for (int q = 0; q < 4; q++) {
                h[q] = __float2bfloat16(vv[q]);
                l[q] = __float2bfloat16(vv[q] - __bfloat162float(h[q]));
            }
            *(__nv_bfloat162*)&Xhi[r * XLD + c4] = __nv_bfloat162{h[0], h[1]};
            *(__nv_bfloat162*)&Xhi[r * XLD + c4 + 2] = __nv_bfloat162{h[2], h[3]};
            *(__nv_bfloat162*)&Xlo[r * XLD + c4] = __nv_bfloat162{l[0], l[1]};
            *(__nv_bfloat162*)&Xlo[r * XLD + c4 + 2] = __nv_bfloat162{l[2], l[3]};
        }
        __syncthreads();

        wmma::fragment<wmma::accumulator, 16, 16, 16, float> acc[2][4];
#pragma unroll
        for (int i = 0; i < 2; i++)
#pragma unroll
            for (int j = 0; j < 4; j++) {
                if (bias)
                    wmma::load_matrix_sync(acc[i][j], &Bs[0][warp_col + j * 16], WLD,
                                           wmma::mem_row_major);
                else
                    wmma::fill_fragment(acc[i][j], 0.f);
            }

#pragma unroll 2
        for (int ks = 0; ks < K; ks += 16) {
            wmma::fragment<wmma::matrix_a, 16, 16, 16, __nv_bfloat16, wmma::row_major> ahi[2], alo[2];
            wmma::fragment<wmma::matrix_b, 16, 16, 16, __nv_bfloat16, wmma::row_major> bhi[4], blo[4];
#pragma unroll
            for (int i = 0; i < 2; i++) {
                wmma::load_matrix_sync(ahi[i], &Xhi[(warp_row + i * 16) * XLD + ks], XLD);
                wmma::load_matrix_sync(alo[i], &Xlo[(warp_row + i * 16) * XLD + ks], XLD);
            }
#pragma unroll
            for (int j = 0; j < 4; j++) {
                wmma::load_matrix_sync(bhi[j], &Whi[ks * WLD + warp_col + j * 16], WLD);
                wmma::load_matrix_sync(blo[j], &Wlo[ks * WLD + warp_col + j * 16], WLD);
            }
#pragma unroll
            for (int i = 0; i < 2; i++)
#pragma unroll
                for (int j = 0; j < 4; j++) {
                    wmma::mma_sync(acc[i][j], ahi[i], blo[j], acc[i][j]);
                    wmma::mma_sync(acc[i][j], alo[i], bhi[j], acc[i][j]);
                    wmma::mma_sync(acc[i][j], ahi[i], bhi[j], acc[i][j]);
                }
        }

        if (!HOUT) {
            float* out = (float*)outv;
#pragma unroll
            for (int i = 0; i < 2; i++)
#pragma unroll
                for (int j = 0; j < 4; j++) {
                    size_t off = (size_t)(block_row + warp_row + i * 16) * 128 + warp_col + j * 16;
                    wmma::store_matrix_sync(&out[off], acc[i][j], 128, wmma::mem_row_major);
                }
        } else {
            __half* out = (__half*)outv;
            const int r = lane >> 1;
            const int c0 = (lane & 1) * 8;
#pragma unroll
            for (int i = 0; i < 2; i++)
#pragma unroll
                for (int j = 0; j < 4; j++) {
                    wmma::store_matrix_sync(&stg[wid][0][0], acc[i][j], 20,
                                            wmma::mem_row_major);
                    __syncwarp();
                    __half2 hp[4];
#pragma unroll
                    for (int q = 0; q < 4; q++) {
                        float a = stg[wid][r][c0 + 2 * q];
                        float b = stg[wid][r][c0 + 2 * q + 1];
                        hp[q] = __floats2half2_rn(a, b);
                    }
                    size_t off = (size_t)(block_row + warp_row + i * 16 + r) * 128 +
                                 warp_col + j * 16 + c0;
                    uint4 pk;
                    pk.x = *reinterpret_cast<unsigned int*>(&hp[0]);
                    pk.y = *reinterpret_cast<unsigned int*>(&hp[1]);
                    pk.z = *reinterpret_cast<unsigned int*>(&hp[2]);
                    pk.w = *reinterpret_cast<unsigned int*>(&hp[3]);
                    *reinterpret_cast<uint4*>(&out[off]) = pk;
                    __syncwarp();
                }
        }
        __syncthreads();
    }
}

template <int K>
constexpr int gemm_smem_bytes() {
    return (2 * K * 136 + 2 * 128 * (K + 8)) * (int)sizeof(__nv_bfloat16);
}

// ---------------------------------------------------------------------------
__global__ void make_wp_all(
    const float* __restrict__ w0ab, const float* __restrict__ as0ab, const float* __restrict__ ad0ab,
    const float* __restrict__ w0ba, const float* __restrict__ as0ba, const float* __restrict__ ad0ba,
    const float* __restrict__ w1ab, const float* __restrict__ as1ab, const float* __restrict__ ad1ab,
    const float* __restrict__ w1ba, const float* __restrict__ as1ba, const float* __restrict__ ad1ba) {
    __shared__ float Ws[64][129];
    int cfg = blockIdx.x;
    const float* W = cfg == 0 ? w0ab : cfg == 1 ? w0ba : cfg == 2 ? w1ab : w1ba;
    const float* avs = cfg == 0 ? as0ab : cfg == 1 ? as0ba : cfg == 2 ? as1ab : as1ba;
    const float* avd = cfg == 0 ? ad0ab : cfg == 1 ? ad0ba : cfg == 2 ? ad1ab : ad1ba;
    const int H = (cfg < 2) ? 4 : 1;
    const int D = 128 / H;
    float* wpS = g_wp[cfg * 2];
    float* wpD = g_wp[cfg * 2 + 1];

    int tid = threadIdx.x;
    float ss[4] = {0.f, 0.f, 0.f, 0.f}, sd[4] = {0.f, 0.f, 0.f, 0.f};
    for (int chunk = 0; chunk < 2; chunk++) {
        int r0 = chunk * 64;
        for (int i = tid; i < 64 * 128; i += 256)
            Ws[i >> 7][i & 127] = W[(size_t)(r0 + (i >> 7)) * 128 + (i & 127)];
        __syncthreads();
        int k = tid;
        if (k < 128 && k >= r0 && k < r0 + 64) {
            for (int h = 0; h < H; h++) {
                float a = 0.f, b = 0.f;
                for (int d = 0; d < D; d++) {
                    float w = Ws[k - r0][h * D + d];
                    a += w * avs[h * D + d];
                    b += w * avd[h * D + d];
                }
                ss[h] = a; sd[h] = b;
            }
        }
        __syncthreads();
    }
    if (tid < 128)
        for (int h = 0; h < H; h++) { wpS[tid * H + h] = ss[h]; wpD[tid * H + h] = sd[h]; }
}

// ---------------------------------------------------------------------------
// merged layer-0 scores: warps [0,NA) -> A nodes, [NA,NA+NB) -> B nodes
// ---------------------------------------------------------------------------
__global__ void node_scores_both(
    const float* __restrict__ hA, const float* __restrict__ hB,
    const float* __restrict__ wpSA, const float* __restrict__ wpDA,
    const float* __restrict__ wpSB, const float* __restrict__ wpDB,
    float* __restrict__ oSA, float* __restrict__ oDA,
    float* __restrict__ oSB, float* __restrict__ oDB, int NA, int NB) {
    int gw = (blockIdx.x * blockDim.x + threadIdx.x) >> 5;
    int lane = threadIdx.x & 31;
    if (gw >= NA + NB) return;
    int sideB = gw >= NA;
    int n = sideB ? gw - NA : gw;
    const float* X = sideB ? hB : hA;
    const float* wpS = sideB ? wpSB : wpSA;
    const float* wpD = sideB ? wpDB : wpDA;
    float* oS = sideB ? oSB : oSA;
    float* oD = sideB ? oDB : oDA;

    const float* xr = X + (size_t)n * 128;
    float accS[4] = {0, 0, 0, 0}, accD[4] = {0, 0, 0, 0};
#pragma unroll
    for (int kk = 0; kk < 4; kk++) {
        int k = lane + kk * 32;
        float x = xr[k];
#pragma unroll
        for (int h = 0; h < 4; h++) {
            accS[h] += x * wpS[k * 4 + h];
            accD[h] += x * wpD[k * 4 + h];
        }
    }
#pragma unroll
    for (int h = 0; h < 4; h++) { accS[h] = warpSum(accS[h]); accD[h] = warpSum(accD[h]); }
    if (lane == 0) {
#pragma unroll
        for (int h = 0; h < 4; h++) { oS[n * 4 + h] = accS[h]; oD[n * 4 + h] = accD[h]; }
    }
}

// ---------------------------------------------------------------------------
// merged CSR kernels (both directions per launch)
// ---------------------------------------------------------------------------
__global__ void zero2(int* __restrict__ a, int na, int* __restrict__ b, int nb) {
    int i = blockIdx.x * blockDim.x + threadIdx.x;
    if (i < na) a[i] = 0;
    else if (i - na < nb) b[i - na] = 0;
}
__global__ void hist2(const int* __restrict__ dstAB, const int* __restrict__ dstBA,
                      int* __restrict__ degAB, int* __restrict__ degBA, int E) {
    int i = blockIdx.x * blockDim.x + threadIdx.x;
    if (i < E) atomicAdd(&degAB[dstAB[i]], 1);
    else if (i < 2 * E) atomicAdd(&degBA[dstBA[i - E]], 1);
}
__global__ __launch_bounds__(1024) void exscan2(
    const int* __restrict__ degAB, int* __restrict__ rpAB, int* __restrict__ curAB, int NB,
    const int* __restrict__ degBA, int* __restrict__ rpBA, int* __restrict__ curBA, int NA) {
    __shared__ int sums[1024];
    const int* deg = blockIdx.x ? degBA : degAB;
    int* rowptr = blockIdx.x ? rpBA : rpAB;
    int* cursor = blockIdx.x ? curBA : curAB;
    int N = blockIdx.x ? NA : NB;
    int t = threadIdx.x;
    int chunk = (N + 1023) / 1024;
    int b0 = t * chunk;
    int b1 = min(b0 + chunk, N);
    int s = 0;
    for (int i = b0; i < b1; i++) s += deg[i];
    sums[t] = s;
    __syncthreads();
    for (int off = 1; off < 1024; off <<= 1) {
        int v = (t >= off) ? sums[t - off] : 0;
        __syncthreads();
        sums[t] += v;
        __syncthreads();
    }
    int run = (t == 0) ? 0 : sums[t - 1];
    for (int i = b0; i < b1; i++) {
        rowptr[i] = run;
        cursor[i] = run;
        run += deg[i];
    }
    if (t == 1023) rowptr[N] = run;
}
__global__ void fill2(const int* __restrict__ srcAB, const int* __restrict__ dstAB,
                      const int* __restrict__ srcBA, const int* __restrict__ dstBA,
                      int* __restrict__ curAB, int* __restrict__ curBA,
                      int* __restrict__ colAB, int* __restrict__ colBA, int E) {
    int i = blockIdx.x * blockDim.x + threadIdx.x;
    if (i < E) {
        int p = atomicAdd(&curAB[dstAB[i]], 1);
        colAB[p] = srcAB[i];
    } else if (i < 2 * E) {
        int j = i - E;
        int p = atomicAdd(&curBA[dstBA[j]], 1);
        colBA[p] = srcBA[j];
    }
}

// ---------------------------------------------------------------------------
// merged fused GAT aggregate (both directions, warp-per-dst-node)
// ---------------------------------------------------------------------------
__device__ __forceinline__ float4 ldt_half4(const __half* p) {
    uint2 u = *(const uint2*)p;
    __half2 h0 = *reinterpret_cast<__half2*>(&u.x);
    __half2 h1 = *reinterpret_cast<__half2*>(&u.y);
    float2 f0 = __half22float2(h0);
    float2 f1 = __half22float2(h1);
    return make_float4(f0.x, f0.y, f1.x, f1.y);
}

template <int H, bool SC>
__global__ __launch_bounds__(256) void gat_both(
    const int* __restrict__ rp0, const int* __restrict__ src0,
    const float* __restrict__ as0, const float* __restrict__ ad0,
    const __half* __restrict__ t0, const float* __restrict__ b0,
    const float* __restrict__ gm0, const float* __restrict__ bt0,
    const float* __restrict__ hp0, float* __restrict__ ho0,
    const float* __restrict__ wS0, const float* __restrict__ wD0,
    float* __restrict__ oS0, float* __restrict__ oD0, int N0,
    const int* __restrict__ rp1, const int* __restrict__ src1,
    const float* __restrict__ as1p, const float* __restrict__ ad1p,
    const __half* __restrict__ t1_, const float* __restrict__ b1,
    const float* __restrict__ gm1, const float* __restrict__ bt1,
    const float* __restrict__ hp1, float* __restrict__ ho1,
    const float* __restrict__ wS1, const float* __restrict__ wD1,
    float* __restrict__ oS1, float* __restrict__ oD1, int N1) {
    const int D = 128 / H;
    const int CAP = 64;
    __shared__ float s_ex[8][CAP * H];
    __shared__ int s_src[8][CAP];

    int gw = (blockIdx.x * blockDim.x + threadIdx.x) >> 5;
    int w = threadIdx.x >> 5;
    int lane = threadIdx.x & 31;
    if (gw >= N0 + N1) return;
    const int side = (gw >= N0) ? 1 : 0;
    const int node = side ? gw - N0 : gw;

    const int* rowptr = side ? rp1 : rp0;
    const int* srcs = side ? src1 : src0;
    const float* a_s = side ? as1p : as0;
    const float* a_d = side ? ad1p : ad0;
    const __half* tS = side ? t1_ : t0;
    const float* gbias = side ? b1 : b0;
    const float* gamma = side ? gm1 : gm0;
    const float* beta = side ? bt1 : bt0;
    const float* hprev = side ? hp1 : hp0;
    float* hout = side ? ho1 : ho0;
    const float* wpSn = side ? wS1 : wS0;
    const float* wpDn = side ? wD1 : wD0;
    float* outSn = side ? oS1 : oS0;
    float* outDn = side ? oD1 : oD0;

    int start = rowptr[node];
    int end = rowptr[node + 1];
    int deg = end - start;

    float adh[H];
#pragma unroll
    for (int h = 0; h < H; h++) adh[h] = a_d[node * H + h];

    const int hh = (lane * 4) / D;
    float4 acc = make_float4(0.f, 0.f, 0.f, 0.f);

    if (deg <= CAP) {
        float sc[2][H];
        int nIt = (deg + 31) >> 5;
        float mx[H];
#pragma unroll
        for (int h = 0; h < H; h++) mx[h] = -3.0e38f;
#pragma unroll
        for (int i = 0; i < 2; i++) {
            int j = lane + i * 32;
            if (i < nIt && j < deg) {
                int s = srcs[start + j];
                s_src[w][j] = s;
                float av[H];
                if (H == 4) {
                    float4 a4 = *(const float4*)(a_s + (size_t)s * 4);
                    av[0] = a4.x; av[1] = a4.y; av[2] = a4.z; av[3] = a4.w;
                } else {
                    av[0] = a_s[s];
                }
#pragma unroll
                for (int h = 0; h < H; h++) {
                    float v = av[h] + adh[h];
                    v = v > 0.f ? v : 0.2f * v;
                    sc[i][h] = v;
                    mx[h] = fmaxf(mx[h], v);
                }
            }
        }
#pragma unroll
        for (int h = 0; h < H; h++) mx[h] = warpMax(mx[h]);

        float sm[H];
#pragma unroll
        for (int h = 0; h < H; h++) sm[h] = 0.f;
#pragma unroll
        for (int i = 0; i < 2; i++) {
            int j = lane + i * 32;
            if (i < nIt && j < deg) {
#pragma unroll
                for (int h = 0; h < H; h++) {
                    float ex = __expf(sc[i][h] - mx[h]);
                    sm[h] += ex;
                    s_ex[w][j * H + h] = ex;
                }
            }
        }
#pragma unroll
        for (int h = 0; h < H; h++) sm[h] = warpSum(sm[h]);
        float invh;
        if (H == 1) invh = 1.f / (sm[0] + 1e-16f);
        else invh = 1.f / ((hh == 0 ? sm[0] : hh == 1 ? sm[1] : hh == 2 ? sm[2] : sm[3]) + 1e-16f);

        __syncwarp();
        int e = 0;
        for (; e + 8 <= deg; e += 8) {
            float ex0 = s_ex[w][(e + 0) * H + hh];
            float ex1 = s_ex[w][(e + 1) * H + hh];
            float ex2 = s_ex[w][(e + 2) * H + hh];
            float ex3 = s_ex[w][(e + 3) * H + hh];
            float ex4 = s_ex[w][(e + 4) * H + hh];
            float ex5 = s_ex[w][(e + 5) * H + hh];
            float ex6 = s_ex[w][(e + 6) * H + hh];
            float ex7 = s_ex[w][(e + 7) * H + hh];
            int s0 = s_src[w][e + 0], s1 = s_src[w][e + 1];
            int s2 = s_src[w][e + 2], s3 = s_src[w][e + 3];
            int s4 = s_src[w][e + 4], s5 = s_src[w][e + 5];
            int s6 = s_src[w][e + 6], s7 = s_src[w][e + 7];
            float4 v0 = ldt_half4(tS + (size_t)s0 * 128 + lane * 4);
            float4 v1 = ldt_half4(tS + (size_t)s1 * 128 + lane * 4);
            float4 v2 = ldt_half4(tS + (size_t)s2 * 128 + lane * 4);
            float4 v3 = ldt_half4(tS + (size_t)s3 * 128 + lane * 4);
            float4 v4 = ldt_half4(tS + (size_t)s4 * 128 + lane * 4);
            float4 v5 = ldt_half4(tS + (size_t)s5 * 128 + lane * 4);
            float4 v6 = ldt_half4(tS + (size_t)s6 * 128 + lane * 4);
            float4 v7 = ldt_half4(tS + (size_t)s7 * 128 + lane * 4);
            acc.x += v0.x * ex0 + v1.x * ex1 + v2.x * ex2 + v3.x * ex3 +
                     v4.x * ex4 + v5.x * ex5 + v6.x * ex6 + v7.x * ex7;
            acc.y += v0.y * ex0 + v1.y * ex1 + v2.y * ex2 + v3.y * ex3 +
                     v4.y * ex4 + v5.y * ex5 + v6.y * ex6 + v7.y * ex7;
            acc.z += v0.z * ex0 + v1.z * ex1 + v2.z * ex2 + v3.z * ex3 +
                     v4.z * ex4 + v5.z * ex5 + v6.z * ex6 + v7.z * ex7;
            acc.w += v0.w * ex0 + v1.w * ex1 + v2.w * ex2 + v3.w * ex3 +
                     v4.w * ex4 + v5.w * ex5 + v6.w * ex6 + v7.w * ex7;
        }
        for (; e < deg; e++) {
            float ex = s_ex[w][e * H + hh];
            int s = s_src[w][e];
            float4 v = ldt_half4(tS + (size_t)s * 128 + lane * 4);
            acc.x += v.x * ex; acc.y += v.y * ex; acc.z += v.z * ex; acc.w += v.w * ex;
        }
        acc.x *= invh; acc.y *= invh; acc.z *= invh; acc.w *= invh;
    } else {
        float mx[H];
#pragma unroll
        for (int h = 0; h < H; h++) mx[h] = -3.0e38f;
        for (int e = start + lane; e < end; e += 32) {
            int s = srcs[e];
#pragma unroll
            for (int h = 0; h < H; h++) {
                float v = a_s[s * H + h] + adh[h];
                v = v > 0.f ? v : 0.2f * v;
                mx[h] = fmaxf(mx[h], v);
            }
        }
#pragma unroll
        for (int h = 0; h < H; h++) mx[h] = warpMax(mx[h]);
        float sm[H];
#pragma unroll
        for (int h = 0; h < H; h++) sm[h] = 0.f;
        for (int e = start + lane; e < end; e += 32) {
            int s = srcs[e];
#pragma unroll
            for (int h = 0; h < H; h++) {
                float v = a_s[s * H + h] + adh[h];
                v = v > 0.f ? v : 0.2f * v;
                sm[h] += __expf(v - mx[h]);
            }
        }
#pragma unroll
        for (int h = 0; h < H; h++) sm[h] = warpSum(sm[h]);
        float invh;
        if (H == 1) invh = 1.f / (sm[0] + 1e-16f);
        else invh = 1.f / ((hh == 0 ? sm[0] : hh == 1 ? sm[1] : hh == 2 ? sm[2] : sm[3]) + 1e-16f);
        float mxh = (H == 1) ? mx[0] : (hh == 0 ? mx[0] : hh == 1 ? mx[1] : hh == 2 ? mx[2] : mx[3]);
        float adhh = (H == 1) ? adh[0] : (hh == 0 ? adh[0] : hh == 1 ? adh[1] : hh == 2 ? adh[2] : adh[3]);
        for (int e = start; e < end; e++) {
            int s = srcs[e];
            float v = a_s[s * H + hh] + adhh;
            v = v > 0.f ? v : 0.2f * v;
            float ex = __expf(v - mxh);
            float4 t = ldt_half4(tS + (size_t)s * 128 + lane * 4);
            acc.x += t.x * ex; acc.y += t.y * ex; acc.z += t.z * ex; acc.w += t.w * ex;
        }
        acc.x *= invh; acc.y *= invh; acc.z *= invh; acc.w *= invh;
    }

    size_t rbase = (size_t)node * 128 + lane * 4;
    float4 bb = *(const float4*)(gbias + lane * 4);
    acc.x += bb.x; acc.y += bb.y; acc.z += bb.z; acc.w += bb.w;
    float mu = warpSum(acc.x + acc.y + acc.z + acc.w) * (1.f / 128.f);
    float dx = acc.x - mu, dy = acc.y - mu, dz = acc.z - mu, dw = acc.w - mu;
    float var = warpSum(dx * dx + dy * dy + dz * dz + dw * dw) * (1.f / 128.f);
    float r = rsqrtf(var + 1e-5f);
    float4 gg = *(const float4*)(gamma + lane * 4);
    float4 be = *(const float4*)(beta + lane * 4);
    float4 hp = *(const float4*)(hprev + rbase);
    float4 o;
    o.x = fmaxf(0.f, dx * r * gg.x + be.x) + hp.x;
    o.y = fmaxf(0.f, dy * r * gg.y + be.y) + hp.y;
    o.z = fmaxf(0.f, dz * r * gg.z + be.z) + hp.z;
    o.w = fmaxf(0.f, dw * r * gg.w + be.w) + hp.w;
    *(float4*)(hout + rbase) = o;

    if (SC) {
        float4 ws = *(const float4*)(wpSn + lane * 4);
        float4 wd = *(const float4*)(wpDn + lane * 4);
        float sS = o.x * ws.x + o.y * ws.y + o.z * ws.z + o.w * ws.w;
        float sD = o.x * wd.x + o.y * wd.y + o.z * wd.z + o.w * wd.w;
        sS = warpSum(sS);
        sD = warpSum(sD);
        if (lane == 0) { outSn[node] = sS; outDn[node] = sD; }
    }
}

// ---------------------------------------------------------------------------
static inline void* sym(const void* s) {
    void* p = nullptr;
    cudaGetSymbolAddress(&p, s);
    return p;
}

extern "C" void kernel_launch(void* const* d_in, const int* in_sizes, int n_in,
                              void* d_out, int out_size) {
    const float* x_A = (const float*)d_in[0];
    const float* x_B = (const float*)d_in[1];
    const float* pWA = (const float*)d_in[2];
    const float* pbA = (const float*)d_in[3];
    const float* pWB = (const float*)d_in[4];
    const float* pbB = (const float*)d_in[5];
    const float* w0ab = (const float*)d_in[6];
    const float* as0ab = (const float*)d_in[7];
    const float* ad0ab = (const float*)d_in[8];
    const float* b0ab = (const float*)d_in[9];
    const float* w0ba = (const float*)d_in[10];
    const float* as0ba = (const float*)d_in[11];
    const float* ad0ba = (const float*)d_in[12];
    const float* b0ba = (const float*)d_in[13];
    const float* w1ab = (const float*)d_in[14];
    const float* as1ab = (const float*)d_in[15];
    const float* ad1ab = (const float*)d_in[16];
    const float* b1ab = (const float*)d_in[17];
    const float* w1ba = (const float*)d_in[18];
    const float* as1ba = (const float*)d_in[19];
    const float* ad1ba = (const float*)d_in[20];
    const float* b1ba = (const float*)d_in[21];
    const float* g0A = (const float*)d_in[22];
    const float* bn0A = (const float*)d_in[23];
    const float* g0B = (const float*)d_in[24];
    const float* bn0B = (const float*)d_in[25];
    const float* g1A = (const float*)d_in[26];
    const float* bn1A = (const float*)d_in[27];
    const float* g1B = (const float*)d_in[28];
    const float* bn1B = (const float*)d_in[29];
    const int* ei_AB = (const int*)d_in[30];
    const int* ei_BA = (const int*)d_in[31];

    const int NA = in_sizes[0] / 128;
    const int NB = in_sizes[1] / 64;
    const int E = in_sizes[30] / 2;

    float* hA = (float*)sym(g_hA);
    float* hB = (float*)sym(g_hB);
    __half* t1 = (__half*)sym(g_t1);
    __half* t2 = (__half*)sym(g_t2);
    __half* t3 = (__half*)sym(g_t3);
    __half* t4 = (__half*)sym(g_t4);
    float* as1_0 = (float*)sym(g_as1_0);
    float* ad1_0 = (float*)sym(g_ad1_0);
    float* as2_0 = (float*)sym(g_as2_0);
    float* ad2_0 = (float*)sym(g_ad2_0);
    float* as1_1 = (float*)sym(g_as1_1);
    float* ad1_1 = (float*)sym(g_ad1_1);
    float* as2_1 = (float*)sym(g_as2_1);
    float* ad2_1 = (float*)sym(g_ad2_1);
    float* wp = (float*)sym(g_wp);
    int* rpAB = (int*)sym(g_rpAB);
    int* rpBA = (int*)sym(g_rpBA);
    int* curAB = (int*)sym(g_curAB);
    int* curBA = (int*)sym(g_curBA);
    int* degAB = (int*)sym(g_degAB);
    int* degBA = (int*)sym(g_degBA);
    int* srcAB = (int*)sym(g_srcAB);
    int* srcBA = (int*)sym(g_srcBA);

    float* wpS1_0 = wp + 0 * 512, *wpD1_0 = wp + 1 * 512;
    float* wpS2_0 = wp + 2 * 512, *wpD2_0 = wp + 3 * 512;
    float* wpS1_1 = wp + 4 * 512, *wpD1_1 = wp + 5 * 512;
    float* wpS2_1 = wp + 6 * 512, *wpD2_1 = wp + 7 * 512;

    const int TB = 256;
    const int NT = NA + NB;
    const int wbBoth = (NT * 32 + TB - 1) / TB;
    const int e2b = (2 * E + TB - 1) / TB;
    const int z2b = (NT + TB - 1) / TB;
    const int PG = 148;

    constexpr int SM128 = gemm_smem_bytes<128>();
    constexpr int SM64 = gemm_smem_bytes<64>();

    static bool s_init = false;
    static cudaStream_t s1, s2, s3;
    static cudaEvent_t eRoot, eWP, eCSR, eG2, eA0, eG4, eF1;
    if (!s_init) {
        cudaStreamCreateWithFlags(&s1, cudaStreamNonBlocking);
        cudaStreamCreateWithFlags(&s2, cudaStreamNonBlocking);
        cudaStreamCreateWithFlags(&s3, cudaStreamNonBlocking);
        cudaEventCreateWithFlags(&eRoot, cudaEventDisableTiming);
        cudaEventCreateWithFlags(&eWP, cudaEventDisableTiming);
        cudaEventCreateWithFlags(&eCSR, cudaEventDisableTiming);
        cudaEventCreateWithFlags(&eG2, cudaEventDisableTiming);
        cudaEventCreateWithFlags(&eA0, cudaEventDisableTiming);
        cudaEventCreateWithFlags(&eG4, cudaEventDisableTiming);
        cudaEventCreateWithFlags(&eF1, cudaEventDisableTiming);
        cudaFuncSetAttribute(gemm_wres<128, false>, cudaFuncAttributeMaxDynamicSharedMemorySize, SM128);
        cudaFuncSetAttribute(gemm_wres<128, true>, cudaFuncAttributeMaxDynamicSharedMemorySize, SM128);
        cudaFuncSetAttribute(gemm_wres<64, false>, cudaFuncAttributeMaxDynamicSharedMemorySize, SM64);
        s_init = true;
    }

    float* outA = (float*)d_out;
    float* outB = outA + (size_t)NA * 128;

    // ---- fork ----
    cudaEventRecord(eRoot, 0);
    cudaStreamWaitEvent(s1, eRoot, 0);
    cudaStreamWaitEvent(s2, eRoot, 0);
    cudaStreamWaitEvent(s3, eRoot, 0);

    // s3: wp + merged CSR (both directions)
    make_wp_all<<<4, 256, 0, s3>>>(w0ab, as0ab, ad0ab, w0ba, as0ba, ad0ba,
                                   w1ab, as1ab, ad1ab, w1ba, as1ba, ad1ba);
    cudaEventRecord(eWP, s3);
    zero2<<<z2b, TB, 0, s3>>>(degAB, NB, degBA, NA);
    hist2<<<e2b, TB, 0, s3>>>(ei_AB + E, ei_BA + E, degAB, degBA, E);
    exscan2<<<2, 1024, 0, s3>>>(degAB, rpAB, curAB, NB, degBA, rpBA, curBA, NA);
    fill2<<<e2b, TB, 0, s3>>>(ei_AB, ei_AB + E, ei_BA, ei_BA + E,
                              curAB, curBA, srcAB, srcBA, E);
    cudaEventRecord(eCSR, s3);

    // s1/s2: projection + layer-0 GEMMs
    gemm_wres<128, false><<<PG, TB, SM128, s1>>>(x_A, pWA, pbA, hA, NA);
    gemm_wres<128, true><<<PG, TB, SM128, s1>>>(hA, w0ab, nullptr, t1, NA);
    gemm_wres<64, false><<<PG, TB, SM64, s2>>>(x_B, pWB, pbB, hB, NB);
    gemm_wres<128, true><<<PG, TB, SM128, s2>>>(hB, w0ba, nullptr, t2, NB);
    cudaEventRecord(eG2, s2);

    // merged layer-0 scores on s1 (needs hA, hB, wp)
    cudaStreamWaitEvent(s1, eG2, 0);
    cudaStreamWaitEvent(s1, eWP, 0);
    node_scores_both<<<wbBoth, TB, 0, s1>>>(hA, hB, wpS1_0, wpD2_0, wpS2_0, wpD1_0,
                                            as1_0, ad2_0, as2_0, ad1_0, NA, NB);

    // merged layer-0 aggregate (side0: dst B / AB, side1: dst A / BA)
    cudaStreamWaitEvent(s1, eCSR, 0);
    gat_both<4, true><<<wbBoth, TB, 0, s1>>>(
        rpAB, srcAB, as1_0, ad1_0, t1, b0ab, g0B, bn0B, hB, hB,
        wpS2_1, wpD1_1, as2_1, ad1_1, NB,
        rpBA, srcBA, as2_0, ad2_0, t2, b0ba, g0A, bn0A, hA, hA,
        wpS1_1, wpD2_1, as1_1, ad2_1, NA);
    cudaEventRecord(eA0, s1);

    // layer-1 GEMMs
    gemm_wres<128, true><<<PG, TB, SM128, s1>>>(hA, w1ab, nullptr, t3, NA);
    cudaStreamWaitEvent(s2, eA0, 0);
    gemm_wres<128, true><<<PG, TB, SM128, s2>>>(hB, w1ba, nullptr, t4, NB);
    cudaEventRecord(eG4, s2);

    // merged layer-1 aggregate -> final outputs
    cudaStreamWaitEvent(s1, eG4, 0);
    gat_both<1, false><<<wbBoth, TB, 0, s1>>>(
        rpAB, srcAB, as1_1, ad1_1, t3, b1ab, g1B, bn1B, hB, outB,
        nullptr, nullptr, nullptr, nullptr, NB,
        rpBA, srcBA, as2_1, ad2_1, t4, b1ba, g1A, bn1A, hA, outA,
        nullptr, nullptr, nullptr, nullptr, NA);
    cudaEventRecord(eF1, s1);

    cudaStreamWaitEvent(0, eF1, 0);
}